// round 9
// baseline (speedup 1.0000x reference)
#include <cuda_runtime.h>
#include <math.h>

#define N_NODES 100000
#define N_EDGES 1600000
#define HIDDEN  48
#define ALPHA   0.1f
#define NPB     160         // nodes per block (100000 = 625 * 160)
#define LTHREADS 192        // gather: 12 groups of 16; GEMM: 16 m-slots x 12 quads
#define ECAP    3584        // smem edge-index buffer (mean 2560)
#define SCB     100         // scan blocks
#define SCHUNK  1000        // elements per scan block

// Scratch (__device__ globals: allocation-free rule; zero-initialized at load)
__device__ float g_x0 [N_NODES * HIDDEN];
__device__ float g_h  [N_NODES * HIDDEN];
__device__ float g_hb [N_NODES * HIDDEN];   // ping-pong buffer
__device__ float g_t  [N_NODES * HIDDEN];   // mixed pre-GEMM features
__device__ int   g_cnt[N_NODES];            // ALWAYS zero at launch entry (scanC re-zeroes)
__device__ int   g_row[N_NODES + 1];
__device__ int   g_cur[N_NODES];
__device__ int   g_esrc[N_EDGES];
__device__ int   g_part[SCB];

// ---------------------------------------------------------------------------
// Init (+fused histogram): h0 = relu(x @ W0 + b0); x0 = h0.
// g_cnt is guaranteed zero on entry (see scanC), so hist atomics fuse here.
// ---------------------------------------------------------------------------
__global__ void init_kernel(const float* __restrict__ x,
                            const float* __restrict__ W0,
                            const float* __restrict__ b0,
                            const int* __restrict__ ei) {
    int idx = blockIdx.x * blockDim.x + threadIdx.x;
    if (idx < N_EDGES)
        atomicAdd(&g_cnt[ei[N_EDGES + idx]], 1);
    if (idx >= N_NODES * HIDDEN) return;
    int n = idx / HIDDEN;
    int j = idx - n * HIDDEN;
    float v = x[n * 3 + 0] * W0[0 * HIDDEN + j]
            + x[n * 3 + 1] * W0[1 * HIDDEN + j]
            + x[n * 3 + 2] * W0[2 * HIDDEN + j]
            + b0[j];
    v = fmaxf(v, 0.0f);
    g_x0[idx] = v;
    g_h[idx]  = v;
}

// ---------------------------------------------------------------------------
// Scan A: per-block sums of g_cnt
// ---------------------------------------------------------------------------
__global__ __launch_bounds__(256) void scanA_kernel() {
    __shared__ int s[256];
    int b = blockIdx.x, t = threadIdx.x;
    int sum = 0;
    for (int i = t; i < SCHUNK; i += 256) sum += g_cnt[b * SCHUNK + i];
    s[t] = sum;
    __syncthreads();
    for (int off = 128; off > 0; off >>= 1) {
        if (t < off) s[t] += s[t + off];
        __syncthreads();
    }
    if (t == 0) g_part[b] = s[0];
}

// ---------------------------------------------------------------------------
// Scan C: final exclusive scan; also RE-ZEROES g_cnt for the next launch
// (device globals start zero, so the fused hist in init_kernel stays correct
// on every replay).
// ---------------------------------------------------------------------------
__global__ __launch_bounds__(1024) void scanC_kernel() {
    __shared__ int s[1024];
    __shared__ int sOff;
    int b = blockIdx.x, t = threadIdx.x;
    if (t == 0) sOff = 0;
    __syncthreads();
    if (t < b) atomicAdd(&sOff, g_part[t]);   // b <= 99

    int i = b * SCHUNK + t;
    int c = (t < SCHUNK) ? g_cnt[i] : 0;
    s[t] = c;
    __syncthreads();
    for (int off = 1; off < 1024; off <<= 1) {
        int v = (t >= off) ? s[t - off] : 0;
        __syncthreads();
        s[t] += v;
        __syncthreads();
    }
    int off = sOff;
    if (t < SCHUNK) {
        int excl = s[t] - c + off;
        g_row[i] = excl;
        g_cur[i] = excl;
        g_cnt[i] = 0;                          // reset for next launch/replay
    }
    if (b == SCB - 1 && t == SCHUNK - 1)
        g_row[N_NODES] = s[t] + off;
}

// ---------------------------------------------------------------------------
// CSR build: fill edge source lists (2 edges per thread, int2 loads)
// ---------------------------------------------------------------------------
__global__ void fill_kernel(const int* __restrict__ ei) {
    int t = blockIdx.x * blockDim.x + threadIdx.x;
    if (t >= N_EDGES / 2) return;
    int2 src = reinterpret_cast<const int2*>(ei)[t];
    int2 dst = reinterpret_cast<const int2*>(ei + N_EDGES)[t];
    int p0 = atomicAdd(&g_cur[dst.x], 1);
    g_esrc[p0] = src.x;
    int p1 = atomicAdd(&g_cur[dst.y], 1);
    g_esrc[p1] = src.y;
}

// ---------------------------------------------------------------------------
// Gather: 16-lane groups (12 active lanes cover a full 192B row in ONE
// LDG.128), dynamic node claiming, smem-staged indices, 2-edge unroll.
// Writes t = 0.9*agg + 0.1*x0 to g_t.
// flip=0: read g_h.  flip=1: read g_hb.
// ---------------------------------------------------------------------------
__global__ __launch_bounds__(LTHREADS)
void gather_kernel(int flip) {
    __shared__ int sE[ECAP];                // 14336 B
    __shared__ int sR[NPB + 1];             // 644 B
    __shared__ int sClaim;

    const float* __restrict__ hin = flip ? g_hb : g_h;

    int tid = threadIdx.x;
    int node0 = blockIdx.x * NPB;

    for (int i = tid; i <= NPB; i += LTHREADS)
        sR[i] = g_row[node0 + i];
    if (tid == 0) sClaim = 0;
    __syncthreads();

    int eStart = sR[0];
    int eCount = sR[NPB] - eStart;
    bool inSmem = (eCount <= ECAP);
    if (inSmem) {
        for (int i = tid; i < eCount; i += LTHREADS)
            sE[i] = g_esrc[eStart + i];
    }
    __syncthreads();

    int lane = tid & 31;
    int c = tid & 15;                         // lane owns float4 index c (c<12)
    bool act = (c < 12);
    unsigned mask16 = 0xFFFFu << (lane & 16);

    while (true) {
        int n = 0;
        if (c == 0) n = atomicAdd(&sClaim, 1);
        n = __shfl_sync(mask16, n, 0, 16);
        if (n >= NPB) break;

        int rs = sR[n], re = sR[n + 1];
        float4 acc = make_float4(0.f, 0.f, 0.f, 0.f);

        if (inSmem) {
            int j = rs - eStart, je = re - eStart;
            for (; j + 2 <= je; j += 2) {
                int s0 = sE[j], s1 = sE[j + 1];
                if (act) {
                    float4 v0 = reinterpret_cast<const float4*>(hin + (size_t)s0 * HIDDEN)[c];
                    float4 v1 = reinterpret_cast<const float4*>(hin + (size_t)s1 * HIDDEN)[c];
                    acc.x += v0.x + v1.x; acc.y += v0.y + v1.y;
                    acc.z += v0.z + v1.z; acc.w += v0.w + v1.w;
                }
            }
            if (j < je) {
                int s0 = sE[j];
                if (act) {
                    float4 v0 = reinterpret_cast<const float4*>(hin + (size_t)s0 * HIDDEN)[c];
                    acc.x += v0.x; acc.y += v0.y; acc.z += v0.z; acc.w += v0.w;
                }
            }
        } else {
            int j = rs, je = re;
            for (; j + 2 <= je; j += 2) {
                int s0 = g_esrc[j], s1 = g_esrc[j + 1];
                if (act) {
                    float4 v0 = reinterpret_cast<const float4*>(hin + (size_t)s0 * HIDDEN)[c];
                    float4 v1 = reinterpret_cast<const float4*>(hin + (size_t)s1 * HIDDEN)[c];
                    acc.x += v0.x + v1.x; acc.y += v0.y + v1.y;
                    acc.z += v0.z + v1.z; acc.w += v0.w + v1.w;
                }
            }
            if (j < je) {
                int s0 = g_esrc[j];
                if (act) {
                    float4 v0 = reinterpret_cast<const float4*>(hin + (size_t)s0 * HIDDEN)[c];
                    acc.x += v0.x; acc.y += v0.y; acc.z += v0.z; acc.w += v0.w;
                }
            }
        }

        if (act) {
            size_t nbase = (size_t)(node0 + n) * HIDDEN;
            float4 x0v = reinterpret_cast<const float4*>(g_x0 + nbase)[c];
            float4 t;
            t.x = (1.0f - ALPHA) * acc.x + ALPHA * x0v.x;
            t.y = (1.0f - ALPHA) * acc.y + ALPHA * x0v.y;
            t.z = (1.0f - ALPHA) * acc.z + ALPHA * x0v.z;
            t.w = (1.0f - ALPHA) * acc.w + ALPHA * x0v.w;
            reinterpret_cast<float4*>(g_t + nbase)[c] = t;
        }
    }
}

// ---------------------------------------------------------------------------
// GEMM: h_out = relu((1-beta)*t + beta * t@W). k-vectorized (float4 over 4 k).
// smem ~40KB -> 5 blocks/SM -> single wave.
// flip=0: write g_hb.  flip=1: write g_h.
// ---------------------------------------------------------------------------
__global__ __launch_bounds__(LTHREADS, 5)
void gemm_kernel(const float* __restrict__ convW, float beta, int flip) {
    __shared__ float sW[HIDDEN * HIDDEN];   // 9216 B
    __shared__ float sT[NPB * HIDDEN];      // 30720 B

    float* __restrict__ hout = flip ? g_h : g_hb;

    int tid = threadIdx.x;
    int node0 = blockIdx.x * NPB;
    int base = node0 * HIDDEN;

    #pragma unroll
    for (int i = tid; i < HIDDEN * HIDDEN; i += LTHREADS)
        sW[i] = convW[i];
    {
        const float4* gt4 = reinterpret_cast<const float4*>(g_t + base);
        float4* sT4 = reinterpret_cast<float4*>(sT);
        for (int i = tid; i < NPB * HIDDEN / 4; i += LTHREADS)
            sT4[i] = gt4[i];
    }
    __syncthreads();

    int q = tid % 12;          // output quad
    int m = tid / 12;          // 0..15
    const float4* sW4 = reinterpret_cast<const float4*>(sW);
    const float4* sT4 = reinterpret_cast<const float4*>(sT);
    float ob = 1.0f - beta;

    #pragma unroll
    for (int chunk = 0; chunk < 2; chunk++) {
        float4 acc[5];
        #pragma unroll
        for (int i = 0; i < 5; i++) acc[i] = make_float4(0.f, 0.f, 0.f, 0.f);

        #pragma unroll
        for (int k4 = 0; k4 < 12; k4++) {
            float4 w0 = sW4[(k4 * 4 + 0) * 12 + q];
            float4 w1 = sW4[(k4 * 4 + 1) * 12 + q];
            float4 w2 = sW4[(k4 * 4 + 2) * 12 + q];
            float4 w3 = sW4[(k4 * 4 + 3) * 12 + q];
            #pragma unroll
            for (int i = 0; i < 5; i++) {
                float4 a = sT4[(m + 16 * (chunk * 5 + i)) * 12 + k4];
                acc[i].x = fmaf(a.x, w0.x, fmaf(a.y, w1.x, fmaf(a.z, w2.x, fmaf(a.w, w3.x, acc[i].x))));
                acc[i].y = fmaf(a.x, w0.y, fmaf(a.y, w1.y, fmaf(a.z, w2.y, fmaf(a.w, w3.y, acc[i].y))));
                acc[i].z = fmaf(a.x, w0.z, fmaf(a.y, w1.z, fmaf(a.z, w2.z, fmaf(a.w, w3.z, acc[i].z))));
                acc[i].w = fmaf(a.x, w0.w, fmaf(a.y, w1.w, fmaf(a.z, w2.w, fmaf(a.w, w3.w, acc[i].w))));
            }
        }
        #pragma unroll
        for (int i = 0; i < 5; i++) {
            int n = m + 16 * (chunk * 5 + i);
            float4 t = sT4[n * 12 + q];
            float4 o;
            o.x = fmaxf(ob * t.x + beta * acc[i].x, 0.0f);
            o.y = fmaxf(ob * t.y + beta * acc[i].y, 0.0f);
            o.z = fmaxf(ob * t.z + beta * acc[i].z, 0.0f);
            o.w = fmaxf(ob * t.w + beta * acc[i].w, 0.0f);
            *(reinterpret_cast<float4*>(hout + (size_t)(node0 + n) * HIDDEN) + q) = o;
        }
    }
}

// ---------------------------------------------------------------------------
// Output: z = h @ W1 + b1 ; out = log_softmax(z)   (reads g_h)
// k-vectorized; Z written back into sT (chunked, disjoint rows). Single wave.
// ---------------------------------------------------------------------------
__global__ __launch_bounds__(LTHREADS, 5)
void out_kernel(const float* __restrict__ W1,
                const float* __restrict__ b1,
                float* __restrict__ out) {
    __shared__ float sW[HIDDEN * HIDDEN];   // 9216 B
    __shared__ float sT[NPB * HIDDEN];      // 30720 B (h, then Z in-place)
    __shared__ float sLS[NPB];              // 640 B

    int tid = threadIdx.x;
    int node0 = blockIdx.x * NPB;
    int base = node0 * HIDDEN;

    #pragma unroll
    for (int i = tid; i < HIDDEN * HIDDEN; i += LTHREADS)
        sW[i] = W1[i];
    {
        const float4* gh4 = reinterpret_cast<const float4*>(g_h + base);
        float4* sT4w = reinterpret_cast<float4*>(sT);
        for (int i = tid; i < NPB * HIDDEN / 4; i += LTHREADS)
            sT4w[i] = gh4[i];
    }
    __syncthreads();

    int q = tid % 12;
    int m = tid / 12;
    const float4* sW4 = reinterpret_cast<const float4*>(sW);
    float4* sT4 = reinterpret_cast<float4*>(sT);
    float4 bv = reinterpret_cast<const float4*>(b1)[q];

    #pragma unroll
    for (int chunk = 0; chunk < 2; chunk++) {
        float4 acc[5];
        #pragma unroll
        for (int i = 0; i < 5; i++) acc[i] = bv;

        #pragma unroll
        for (int k4 = 0; k4 < 12; k4++) {
            float4 w0 = sW4[(k4 * 4 + 0) * 12 + q];
            float4 w1 = sW4[(k4 * 4 + 1) * 12 + q];
            float4 w2 = sW4[(k4 * 4 + 2) * 12 + q];
            float4 w3 = sW4[(k4 * 4 + 3) * 12 + q];
            #pragma unroll
            for (int i = 0; i < 5; i++) {
                float4 a = sT4[(m + 16 * (chunk * 5 + i)) * 12 + k4];
                acc[i].x = fmaf(a.x, w0.x, fmaf(a.y, w1.x, fmaf(a.z, w2.x, fmaf(a.w, w3.x, acc[i].x))));
                acc[i].y = fmaf(a.x, w0.y, fmaf(a.y, w1.y, fmaf(a.z, w2.y, fmaf(a.w, w3.y, acc[i].y))));
                acc[i].z = fmaf(a.x, w0.z, fmaf(a.y, w1.z, fmaf(a.z, w2.z, fmaf(a.w, w3.z, acc[i].z))));
                acc[i].w = fmaf(a.x, w0.w, fmaf(a.y, w1.w, fmaf(a.z, w2.w, fmaf(a.w, w3.w, acc[i].w))));
            }
        }
        __syncthreads();   // all reads of this chunk's source rows done
        #pragma unroll
        for (int i = 0; i < 5; i++) {
            int n = m + 16 * (chunk * 5 + i);
            sT4[n * 12 + q] = acc[i];
        }
    }
    __syncthreads();

    if (tid < NPB) {
        float mx = -INFINITY;
        #pragma unroll
        for (int k = 0; k < HIDDEN; k++)
            mx = fmaxf(mx, sT[tid * HIDDEN + k]);
        float s = 0.0f;
        #pragma unroll
        for (int k = 0; k < HIDDEN; k++)
            s += expf(sT[tid * HIDDEN + k] - mx);
        sLS[tid] = mx + logf(s);
    }
    __syncthreads();

    #pragma unroll
    for (int i = 0; i < 10; i++) {
        int n = m + 16 * i;
        float ls = sLS[n];
        float4 z = sT4[n * 12 + q];
        float4 o;
        o.x = z.x - ls; o.y = z.y - ls; o.z = z.z - ls; o.w = z.w - ls;
        *(reinterpret_cast<float4*>(out + (size_t)base + n * HIDDEN) + q) = o;
    }
}

// ---------------------------------------------------------------------------
extern "C" void kernel_launch(void* const* d_in, const int* in_sizes, int n_in,
                              void* d_out, int out_size) {
    const float* x     = (const float*)d_in[0];
    const int*   ei    = (const int*)  d_in[1];
    const float* W0    = (const float*)d_in[2];
    const float* b0    = (const float*)d_in[3];
    const float* convW = (const float*)d_in[4];
    const float* W1    = (const float*)d_in[5];
    const float* b1    = (const float*)d_in[6];
    float* out = (float*)d_out;

    // beta_l = log(0.5/(l+1) + 1)
    const float betas[4] = {0.4054651081f, 0.2231435513f,
                            0.1541506798f, 0.1177830357f};

    const int it = 256;
    init_kernel<<<(N_NODES * HIDDEN + it - 1) / it, it>>>(x, W0, b0, ei);

    scanA_kernel<<<SCB, 256>>>();
    scanC_kernel<<<SCB, 1024>>>();

    const int ft = 256;
    fill_kernel<<<(N_EDGES / 2 + ft - 1) / ft, ft>>>(ei);

    const int node_blocks = N_NODES / NPB;   // 625
    for (int l = 0; l < 4; l++) {
        gather_kernel<<<node_blocks, LTHREADS>>>(l & 1);
        gemm_kernel<<<node_blocks, LTHREADS>>>(convW + l * HIDDEN * HIDDEN,
                                               betas[l], l & 1);
    }

    // layers 0..3: h path g_h -> g_hb -> g_h -> g_hb -> g_h (final in g_h)
    out_kernel<<<node_blocks, LTHREADS>>>(W1, b1, out);
}

// round 10
// speedup vs baseline: 1.0837x; 1.0837x over previous
#include <cuda_runtime.h>
#include <math.h>

#define N_NODES 100000
#define N_EDGES 1600000
#define HIDDEN  48
#define ALPHA   0.1f
#define NPB     160         // nodes per block (100000 = 625 * 160)
#define LTHREADS 192        // GEMM/out: 16 m-slots x 12 quads
#define GTHREADS 256        // gather: 64 groups of 4 lanes
#define ECAP    3584        // smem edge-index buffer (mean 2560)
#define SCB     100         // scan blocks
#define SCHUNK  1000        // elements per scan block

// Scratch (__device__ globals: allocation-free rule; zero-initialized at load)
__device__ float g_x0 [N_NODES * HIDDEN];
__device__ float g_h  [N_NODES * HIDDEN];
__device__ float g_hb [N_NODES * HIDDEN];   // ping-pong buffer
__device__ float g_t  [N_NODES * HIDDEN];   // mixed pre-GEMM features
__device__ int   g_cnt[N_NODES];            // ALWAYS zero at launch entry (scanC re-zeroes)
__device__ int   g_row[N_NODES + 1];
__device__ int   g_cur[N_NODES];
__device__ int   g_esrc[N_EDGES];
__device__ int   g_part[SCB];

// ---------------------------------------------------------------------------
// Init (+fused histogram): h0 = relu(x @ W0 + b0); x0 = h0.
// g_cnt is guaranteed zero on entry (see scanC), so hist atomics fuse here.
// ---------------------------------------------------------------------------
__global__ void init_kernel(const float* __restrict__ x,
                            const float* __restrict__ W0,
                            const float* __restrict__ b0,
                            const int* __restrict__ ei) {
    int idx = blockIdx.x * blockDim.x + threadIdx.x;
    if (idx < N_EDGES)
        atomicAdd(&g_cnt[ei[N_EDGES + idx]], 1);
    if (idx >= N_NODES * HIDDEN) return;
    int n = idx / HIDDEN;
    int j = idx - n * HIDDEN;
    float v = x[n * 3 + 0] * W0[0 * HIDDEN + j]
            + x[n * 3 + 1] * W0[1 * HIDDEN + j]
            + x[n * 3 + 2] * W0[2 * HIDDEN + j]
            + b0[j];
    v = fmaxf(v, 0.0f);
    g_x0[idx] = v;
    g_h[idx]  = v;
}

// ---------------------------------------------------------------------------
// Scan A: per-block sums of g_cnt
// ---------------------------------------------------------------------------
__global__ __launch_bounds__(256) void scanA_kernel() {
    __shared__ int s[256];
    int b = blockIdx.x, t = threadIdx.x;
    int sum = 0;
    for (int i = t; i < SCHUNK; i += 256) sum += g_cnt[b * SCHUNK + i];
    s[t] = sum;
    __syncthreads();
    for (int off = 128; off > 0; off >>= 1) {
        if (t < off) s[t] += s[t + off];
        __syncthreads();
    }
    if (t == 0) g_part[b] = s[0];
}

// ---------------------------------------------------------------------------
// Scan C: final exclusive scan; also RE-ZEROES g_cnt for the next launch.
// ---------------------------------------------------------------------------
__global__ __launch_bounds__(1024) void scanC_kernel() {
    __shared__ int s[1024];
    __shared__ int sOff;
    int b = blockIdx.x, t = threadIdx.x;
    if (t == 0) sOff = 0;
    __syncthreads();
    if (t < b) atomicAdd(&sOff, g_part[t]);   // b <= 99

    int i = b * SCHUNK + t;
    int c = (t < SCHUNK) ? g_cnt[i] : 0;
    s[t] = c;
    __syncthreads();
    for (int off = 1; off < 1024; off <<= 1) {
        int v = (t >= off) ? s[t - off] : 0;
        __syncthreads();
        s[t] += v;
        __syncthreads();
    }
    int off = sOff;
    if (t < SCHUNK) {
        int excl = s[t] - c + off;
        g_row[i] = excl;
        g_cur[i] = excl;
        g_cnt[i] = 0;                          // reset for next launch/replay
    }
    if (b == SCB - 1 && t == SCHUNK - 1)
        g_row[N_NODES] = s[t] + off;
}

// ---------------------------------------------------------------------------
// CSR build: fill edge source lists (2 edges per thread, int2 loads)
// ---------------------------------------------------------------------------
__global__ void fill_kernel(const int* __restrict__ ei) {
    int t = blockIdx.x * blockDim.x + threadIdx.x;
    if (t >= N_EDGES / 2) return;
    int2 src = reinterpret_cast<const int2*>(ei)[t];
    int2 dst = reinterpret_cast<const int2*>(ei + N_EDGES)[t];
    int p0 = atomicAdd(&g_cur[dst.x], 1);
    g_esrc[p0] = src.x;
    int p1 = atomicAdd(&g_cur[dst.y], 1);
    g_esrc[p1] = src.y;
}

__device__ __forceinline__ void f4add(float4& a, const float4& b) {
    a.x += b.x; a.y += b.y; a.z += b.z; a.w += b.w;
}
__device__ __forceinline__ void f4add2(float4& a, const float4& b, const float4& c) {
    a.x += b.x + c.x; a.y += b.y + c.y; a.z += b.z + c.z; a.w += b.w + c.w;
}

// ---------------------------------------------------------------------------
// Gather (Round-8 proven form, wider block): 4-lane groups with INTERLEAVED
// ownership (lane c owns float4 idx {c, c+4, c+8} -> each LDG.128 covers a
// contiguous 64B per group), dynamic node claiming, smem-staged indices,
// 2-edge unroll. 64 groups/block for high MLP.
// Writes t = 0.9*agg + 0.1*x0 to g_t.
// flip=0: read g_h.  flip=1: read g_hb.
// ---------------------------------------------------------------------------
__global__ __launch_bounds__(GTHREADS)
void gather_kernel(int flip) {
    __shared__ int sE[ECAP];                // 14336 B
    __shared__ int sR[NPB + 1];             // 644 B
    __shared__ int sClaim;

    const float* __restrict__ hin = flip ? g_hb : g_h;

    int tid = threadIdx.x;
    int node0 = blockIdx.x * NPB;

    for (int i = tid; i <= NPB; i += GTHREADS)
        sR[i] = g_row[node0 + i];
    if (tid == 0) sClaim = 0;
    __syncthreads();

    int eStart = sR[0];
    int eCount = sR[NPB] - eStart;
    bool inSmem = (eCount <= ECAP);
    if (inSmem) {
        for (int i = tid; i < eCount; i += GTHREADS)
            sE[i] = g_esrc[eStart + i];
    }
    __syncthreads();

    int lane = tid & 31;
    int c = tid & 3;                          // interleave: float4 idx c, c+4, c+8
    unsigned submask = 0xFu << (lane & ~3);

    while (true) {
        int n = 0;
        if (c == 0) n = atomicAdd(&sClaim, 1);
        n = __shfl_sync(submask, n, 0, 4);
        if (n >= NPB) break;

        int rs = sR[n], re = sR[n + 1];
        float4 a0 = make_float4(0.f, 0.f, 0.f, 0.f);
        float4 a1 = a0, a2 = a0;

        if (inSmem) {
            int j = rs - eStart, je = re - eStart;
            for (; j + 2 <= je; j += 2) {
                int s0 = sE[j], s1 = sE[j + 1];
                const float4* p0 = reinterpret_cast<const float4*>(hin + (size_t)s0 * HIDDEN) + c;
                const float4* p1 = reinterpret_cast<const float4*>(hin + (size_t)s1 * HIDDEN) + c;
                float4 u0 = p0[0], u1 = p0[4], u2 = p0[8];
                float4 w0 = p1[0], w1 = p1[4], w2 = p1[8];
                f4add2(a0, u0, w0); f4add2(a1, u1, w1); f4add2(a2, u2, w2);
            }
            if (j < je) {
                int s0 = sE[j];
                const float4* p0 = reinterpret_cast<const float4*>(hin + (size_t)s0 * HIDDEN) + c;
                f4add(a0, p0[0]); f4add(a1, p0[4]); f4add(a2, p0[8]);
            }
        } else {
            int j = rs, je = re;
            for (; j + 2 <= je; j += 2) {
                int s0 = g_esrc[j], s1 = g_esrc[j + 1];
                const float4* p0 = reinterpret_cast<const float4*>(hin + (size_t)s0 * HIDDEN) + c;
                const float4* p1 = reinterpret_cast<const float4*>(hin + (size_t)s1 * HIDDEN) + c;
                float4 u0 = p0[0], u1 = p0[4], u2 = p0[8];
                float4 w0 = p1[0], w1 = p1[4], w2 = p1[8];
                f4add2(a0, u0, w0); f4add2(a1, u1, w1); f4add2(a2, u2, w2);
            }
            if (j < je) {
                int s0 = g_esrc[j];
                const float4* p0 = reinterpret_cast<const float4*>(hin + (size_t)s0 * HIDDEN) + c;
                f4add(a0, p0[0]); f4add(a1, p0[4]); f4add(a2, p0[8]);
            }
        }

        size_t nbase = (size_t)(node0 + n) * HIDDEN;
        const float4* px = reinterpret_cast<const float4*>(g_x0 + nbase) + c;
        float4 x0v0 = px[0], x0v1 = px[4], x0v2 = px[8];
        float4 t0, t1, t2;
        t0.x = (1.0f - ALPHA) * a0.x + ALPHA * x0v0.x;
        t0.y = (1.0f - ALPHA) * a0.y + ALPHA * x0v0.y;
        t0.z = (1.0f - ALPHA) * a0.z + ALPHA * x0v0.z;
        t0.w = (1.0f - ALPHA) * a0.w + ALPHA * x0v0.w;
        t1.x = (1.0f - ALPHA) * a1.x + ALPHA * x0v1.x;
        t1.y = (1.0f - ALPHA) * a1.y + ALPHA * x0v1.y;
        t1.z = (1.0f - ALPHA) * a1.z + ALPHA * x0v1.z;
        t1.w = (1.0f - ALPHA) * a1.w + ALPHA * x0v1.w;
        t2.x = (1.0f - ALPHA) * a2.x + ALPHA * x0v2.x;
        t2.y = (1.0f - ALPHA) * a2.y + ALPHA * x0v2.y;
        t2.z = (1.0f - ALPHA) * a2.z + ALPHA * x0v2.z;
        t2.w = (1.0f - ALPHA) * a2.w + ALPHA * x0v2.w;
        float4* pt = reinterpret_cast<float4*>(g_t + nbase) + c;
        pt[0] = t0; pt[4] = t1; pt[8] = t2;
    }
}

// ---------------------------------------------------------------------------
// GEMM: h_out = relu((1-beta)*t + beta * t@W). k-vectorized (float4 over 4 k).
// smem ~40KB -> 5 blocks/SM -> single wave.
// flip=0: write g_hb.  flip=1: write g_h.
// ---------------------------------------------------------------------------
__global__ __launch_bounds__(LTHREADS, 5)
void gemm_kernel(const float* __restrict__ convW, float beta, int flip) {
    __shared__ float sW[HIDDEN * HIDDEN];   // 9216 B
    __shared__ float sT[NPB * HIDDEN];      // 30720 B

    float* __restrict__ hout = flip ? g_h : g_hb;

    int tid = threadIdx.x;
    int node0 = blockIdx.x * NPB;
    int base = node0 * HIDDEN;

    #pragma unroll
    for (int i = tid; i < HIDDEN * HIDDEN; i += LTHREADS)
        sW[i] = convW[i];
    {
        const float4* gt4 = reinterpret_cast<const float4*>(g_t + base);
        float4* sT4w = reinterpret_cast<float4*>(sT);
        for (int i = tid; i < NPB * HIDDEN / 4; i += LTHREADS)
            sT4w[i] = gt4[i];
    }
    __syncthreads();

    int q = tid % 12;          // output quad
    int m = tid / 12;          // 0..15
    const float4* sW4 = reinterpret_cast<const float4*>(sW);
    const float4* sT4 = reinterpret_cast<const float4*>(sT);
    float ob = 1.0f - beta;

    #pragma unroll
    for (int chunk = 0; chunk < 2; chunk++) {
        float4 acc[5];
        #pragma unroll
        for (int i = 0; i < 5; i++) acc[i] = make_float4(0.f, 0.f, 0.f, 0.f);

        #pragma unroll
        for (int k4 = 0; k4 < 12; k4++) {
            float4 w0 = sW4[(k4 * 4 + 0) * 12 + q];
            float4 w1 = sW4[(k4 * 4 + 1) * 12 + q];
            float4 w2 = sW4[(k4 * 4 + 2) * 12 + q];
            float4 w3 = sW4[(k4 * 4 + 3) * 12 + q];
            #pragma unroll
            for (int i = 0; i < 5; i++) {
                float4 a = sT4[(m + 16 * (chunk * 5 + i)) * 12 + k4];
                acc[i].x = fmaf(a.x, w0.x, fmaf(a.y, w1.x, fmaf(a.z, w2.x, fmaf(a.w, w3.x, acc[i].x))));
                acc[i].y = fmaf(a.x, w0.y, fmaf(a.y, w1.y, fmaf(a.z, w2.y, fmaf(a.w, w3.y, acc[i].y))));
                acc[i].z = fmaf(a.x, w0.z, fmaf(a.y, w1.z, fmaf(a.z, w2.z, fmaf(a.w, w3.z, acc[i].z))));
                acc[i].w = fmaf(a.x, w0.w, fmaf(a.y, w1.w, fmaf(a.z, w2.w, fmaf(a.w, w3.w, acc[i].w))));
            }
        }
        #pragma unroll
        for (int i = 0; i < 5; i++) {
            int n = m + 16 * (chunk * 5 + i);
            float4 t = sT4[n * 12 + q];
            float4 o;
            o.x = fmaxf(ob * t.x + beta * acc[i].x, 0.0f);
            o.y = fmaxf(ob * t.y + beta * acc[i].y, 0.0f);
            o.z = fmaxf(ob * t.z + beta * acc[i].z, 0.0f);
            o.w = fmaxf(ob * t.w + beta * acc[i].w, 0.0f);
            *(reinterpret_cast<float4*>(hout + (size_t)(node0 + n) * HIDDEN) + q) = o;
        }
    }
}

// ---------------------------------------------------------------------------
// Output: z = h @ W1 + b1 ; out = log_softmax(z)   (reads g_h)
// k-vectorized; Z written back into sT (chunked, disjoint rows). Single wave.
// ---------------------------------------------------------------------------
__global__ __launch_bounds__(LTHREADS, 5)
void out_kernel(const float* __restrict__ W1,
                const float* __restrict__ b1,
                float* __restrict__ out) {
    __shared__ float sW[HIDDEN * HIDDEN];   // 9216 B
    __shared__ float sT[NPB * HIDDEN];      // 30720 B (h, then Z in-place)
    __shared__ float sLS[NPB];              // 640 B

    int tid = threadIdx.x;
    int node0 = blockIdx.x * NPB;
    int base = node0 * HIDDEN;

    #pragma unroll
    for (int i = tid; i < HIDDEN * HIDDEN; i += LTHREADS)
        sW[i] = W1[i];
    {
        const float4* gh4 = reinterpret_cast<const float4*>(g_h + base);
        float4* sT4w = reinterpret_cast<float4*>(sT);
        for (int i = tid; i < NPB * HIDDEN / 4; i += LTHREADS)
            sT4w[i] = gh4[i];
    }
    __syncthreads();

    int q = tid % 12;
    int m = tid / 12;
    const float4* sW4 = reinterpret_cast<const float4*>(sW);
    float4* sT4 = reinterpret_cast<float4*>(sT);
    float4 bv = reinterpret_cast<const float4*>(b1)[q];

    #pragma unroll
    for (int chunk = 0; chunk < 2; chunk++) {
        float4 acc[5];
        #pragma unroll
        for (int i = 0; i < 5; i++) acc[i] = bv;

        #pragma unroll
        for (int k4 = 0; k4 < 12; k4++) {
            float4 w0 = sW4[(k4 * 4 + 0) * 12 + q];
            float4 w1 = sW4[(k4 * 4 + 1) * 12 + q];
            float4 w2 = sW4[(k4 * 4 + 2) * 12 + q];
            float4 w3 = sW4[(k4 * 4 + 3) * 12 + q];
            #pragma unroll
            for (int i = 0; i < 5; i++) {
                float4 a = sT4[(m + 16 * (chunk * 5 + i)) * 12 + k4];
                acc[i].x = fmaf(a.x, w0.x, fmaf(a.y, w1.x, fmaf(a.z, w2.x, fmaf(a.w, w3.x, acc[i].x))));
                acc[i].y = fmaf(a.x, w0.y, fmaf(a.y, w1.y, fmaf(a.z, w2.y, fmaf(a.w, w3.y, acc[i].y))));
                acc[i].z = fmaf(a.x, w0.z, fmaf(a.y, w1.z, fmaf(a.z, w2.z, fmaf(a.w, w3.z, acc[i].z))));
                acc[i].w = fmaf(a.x, w0.w, fmaf(a.y, w1.w, fmaf(a.z, w2.w, fmaf(a.w, w3.w, acc[i].w))));
            }
        }
        __syncthreads();   // all reads of this chunk's source rows done
        #pragma unroll
        for (int i = 0; i < 5; i++) {
            int n = m + 16 * (chunk * 5 + i);
            sT4[n * 12 + q] = acc[i];
        }
    }
    __syncthreads();

    if (tid < NPB) {
        float mx = -INFINITY;
        #pragma unroll
        for (int k = 0; k < HIDDEN; k++)
            mx = fmaxf(mx, sT[tid * HIDDEN + k]);
        float s = 0.0f;
        #pragma unroll
        for (int k = 0; k < HIDDEN; k++)
            s += expf(sT[tid * HIDDEN + k] - mx);
        sLS[tid] = mx + logf(s);
    }
    __syncthreads();

    #pragma unroll
    for (int i = 0; i < 10; i++) {
        int n = m + 16 * i;
        float ls = sLS[n];
        float4 z = sT4[n * 12 + q];
        float4 o;
        o.x = z.x - ls; o.y = z.y - ls; o.z = z.z - ls; o.w = z.w - ls;
        *(reinterpret_cast<float4*>(out + (size_t)base + n * HIDDEN) + q) = o;
    }
}

// ---------------------------------------------------------------------------
extern "C" void kernel_launch(void* const* d_in, const int* in_sizes, int n_in,
                              void* d_out, int out_size) {
    const float* x     = (const float*)d_in[0];
    const int*   ei    = (const int*)  d_in[1];
    const float* W0    = (const float*)d_in[2];
    const float* b0    = (const float*)d_in[3];
    const float* convW = (const float*)d_in[4];
    const float* W1    = (const float*)d_in[5];
    const float* b1    = (const float*)d_in[6];
    float* out = (float*)d_out;

    // beta_l = log(0.5/(l+1) + 1)
    const float betas[4] = {0.4054651081f, 0.2231435513f,
                            0.1541506798f, 0.1177830357f};

    const int it = 256;
    init_kernel<<<(N_NODES * HIDDEN + it - 1) / it, it>>>(x, W0, b0, ei);

    scanA_kernel<<<SCB, 256>>>();
    scanC_kernel<<<SCB, 1024>>>();

    const int ft = 256;
    fill_kernel<<<(N_EDGES / 2 + ft - 1) / ft, ft>>>(ei);

    const int node_blocks = N_NODES / NPB;   // 625
    for (int l = 0; l < 4; l++) {
        gather_kernel<<<node_blocks, GTHREADS>>>(l & 1);
        gemm_kernel<<<node_blocks, LTHREADS>>>(convW + l * HIDDEN * HIDDEN,
                                               betas[l], l & 1);
    }

    // layers 0..3: h path g_h -> g_hb -> g_h -> g_hb -> g_h (final in g_h)
    out_kernel<<<node_blocks, LTHREADS>>>(W1, b1, out);
}

// round 11
// speedup vs baseline: 1.7381x; 1.6038x over previous
#include <cuda_runtime.h>
#include <math.h>

#define N_NODES 100000
#define N_EDGES 1600000
#define HIDDEN  48
#define ALPHA   0.1f
#define NPB     160         // nodes per block (100000 = 625 * 160)
#define LTHREADS 192        // gather: 48 groups of 4; GEMM: 16 m-slots x 12 quads
#define ECAP    3584        // smem edge-index buffer (mean 2560)
#define SCB     100         // scan blocks
#define SCHUNK  1000        // elements per scan block

// Scratch (__device__ globals: allocation-free rule; zero-initialized at load)
__device__ float g_x0 [N_NODES * HIDDEN];
__device__ float g_h  [N_NODES * HIDDEN];
__device__ float g_hb [N_NODES * HIDDEN];   // ping-pong buffer
__device__ float g_t  [N_NODES * HIDDEN];   // mixed pre-GEMM features
__device__ int   g_cnt[N_NODES];            // ALWAYS zero at launch entry (scanC re-zeroes)
__device__ int   g_row[N_NODES + 1];
__device__ int   g_cur[N_NODES];
__device__ int   g_esrc[N_EDGES];
__device__ int   g_part[SCB];

// ---------------------------------------------------------------------------
// Init (+fused histogram): h0 = relu(x @ W0 + b0); x0 = h0.
// g_cnt is guaranteed zero on entry (see scanC), so hist atomics fuse here.
// ---------------------------------------------------------------------------
__global__ void init_kernel(const float* __restrict__ x,
                            const float* __restrict__ W0,
                            const float* __restrict__ b0,
                            const int* __restrict__ ei) {
    int idx = blockIdx.x * blockDim.x + threadIdx.x;
    if (idx < N_EDGES)
        atomicAdd(&g_cnt[ei[N_EDGES + idx]], 1);
    if (idx >= N_NODES * HIDDEN) return;
    int n = idx / HIDDEN;
    int j = idx - n * HIDDEN;
    float v = x[n * 3 + 0] * W0[0 * HIDDEN + j]
            + x[n * 3 + 1] * W0[1 * HIDDEN + j]
            + x[n * 3 + 2] * W0[2 * HIDDEN + j]
            + b0[j];
    v = fmaxf(v, 0.0f);
    g_x0[idx] = v;
    g_h[idx]  = v;
}

// ---------------------------------------------------------------------------
// Scan A: per-block sums of g_cnt
// ---------------------------------------------------------------------------
__global__ __launch_bounds__(256) void scanA_kernel() {
    __shared__ int s[256];
    int b = blockIdx.x, t = threadIdx.x;
    int sum = 0;
    for (int i = t; i < SCHUNK; i += 256) sum += g_cnt[b * SCHUNK + i];
    s[t] = sum;
    __syncthreads();
    for (int off = 128; off > 0; off >>= 1) {
        if (t < off) s[t] += s[t + off];
        __syncthreads();
    }
    if (t == 0) g_part[b] = s[0];
}

// ---------------------------------------------------------------------------
// Scan C: final exclusive scan; also RE-ZEROES g_cnt for the next launch.
// ---------------------------------------------------------------------------
__global__ __launch_bounds__(1024) void scanC_kernel() {
    __shared__ int s[1024];
    __shared__ int sOff;
    int b = blockIdx.x, t = threadIdx.x;
    if (t == 0) sOff = 0;
    __syncthreads();
    if (t < b) atomicAdd(&sOff, g_part[t]);   // b <= 99

    int i = b * SCHUNK + t;
    int c = (t < SCHUNK) ? g_cnt[i] : 0;
    s[t] = c;
    __syncthreads();
    for (int off = 1; off < 1024; off <<= 1) {
        int v = (t >= off) ? s[t - off] : 0;
        __syncthreads();
        s[t] += v;
        __syncthreads();
    }
    int off = sOff;
    if (t < SCHUNK) {
        int excl = s[t] - c + off;
        g_row[i] = excl;
        g_cur[i] = excl;
        g_cnt[i] = 0;                          // reset for next launch/replay
    }
    if (b == SCB - 1 && t == SCHUNK - 1)
        g_row[N_NODES] = s[t] + off;
}

// ---------------------------------------------------------------------------
// CSR build: fill edge source lists (2 edges per thread, int2 loads)
// ---------------------------------------------------------------------------
__global__ void fill_kernel(const int* __restrict__ ei) {
    int t = blockIdx.x * blockDim.x + threadIdx.x;
    if (t >= N_EDGES / 2) return;
    int2 src = reinterpret_cast<const int2*>(ei)[t];
    int2 dst = reinterpret_cast<const int2*>(ei + N_EDGES)[t];
    int p0 = atomicAdd(&g_cur[dst.x], 1);
    g_esrc[p0] = src.x;
    int p1 = atomicAdd(&g_cur[dst.y], 1);
    g_esrc[p1] = src.y;
}

__device__ __forceinline__ void f4add(float4& a, const float4& b) {
    a.x += b.x; a.y += b.y; a.z += b.z; a.w += b.w;
}
__device__ __forceinline__ void f4add2(float4& a, const float4& b, const float4& c) {
    a.x += b.x + c.x; a.y += b.y + c.y; a.z += b.z + c.z; a.w += b.w + c.w;
}

// ---------------------------------------------------------------------------
// Gather (EXACT Round-8 winning form): 4-lane groups with INTERLEAVED
// ownership (lane c owns float4 idx {c, c+4, c+8}), dynamic node claiming,
// smem-staged indices, 2-edge unroll, 192 threads (48 groups/block).
// Writes t = 0.9*agg + 0.1*x0 to g_t.
// flip=0: read g_h.  flip=1: read g_hb.
// ---------------------------------------------------------------------------
__global__ __launch_bounds__(LTHREADS)
void gather_kernel(int flip) {
    __shared__ int sE[ECAP];                // 14336 B
    __shared__ int sR[NPB + 1];             // 644 B
    __shared__ int sClaim;

    const float* __restrict__ hin = flip ? g_hb : g_h;

    int tid = threadIdx.x;
    int node0 = blockIdx.x * NPB;

    for (int i = tid; i <= NPB; i += LTHREADS)
        sR[i] = g_row[node0 + i];
    if (tid == 0) sClaim = 0;
    __syncthreads();

    int eStart = sR[0];
    int eCount = sR[NPB] - eStart;
    bool inSmem = (eCount <= ECAP);
    if (inSmem) {
        for (int i = tid; i < eCount; i += LTHREADS)
            sE[i] = g_esrc[eStart + i];
    }
    __syncthreads();

    int lane = tid & 31;
    int c = tid & 3;                          // interleave: float4 idx c, c+4, c+8
    unsigned submask = 0xFu << (lane & ~3);

    while (true) {
        int n = 0;
        if (c == 0) n = atomicAdd(&sClaim, 1);
        n = __shfl_sync(submask, n, 0, 4);
        if (n >= NPB) break;

        int rs = sR[n], re = sR[n + 1];
        float4 a0 = make_float4(0.f, 0.f, 0.f, 0.f);
        float4 a1 = a0, a2 = a0;

        if (inSmem) {
            int j = rs - eStart, je = re - eStart;
            for (; j + 2 <= je; j += 2) {
                int s0 = sE[j], s1 = sE[j + 1];
                const float4* p0 = reinterpret_cast<const float4*>(hin + (size_t)s0 * HIDDEN) + c;
                const float4* p1 = reinterpret_cast<const float4*>(hin + (size_t)s1 * HIDDEN) + c;
                float4 u0 = p0[0], u1 = p0[4], u2 = p0[8];
                float4 w0 = p1[0], w1 = p1[4], w2 = p1[8];
                f4add2(a0, u0, w0); f4add2(a1, u1, w1); f4add2(a2, u2, w2);
            }
            if (j < je) {
                int s0 = sE[j];
                const float4* p0 = reinterpret_cast<const float4*>(hin + (size_t)s0 * HIDDEN) + c;
                f4add(a0, p0[0]); f4add(a1, p0[4]); f4add(a2, p0[8]);
            }
        } else {
            int j = rs, je = re;
            for (; j + 2 <= je; j += 2) {
                int s0 = g_esrc[j], s1 = g_esrc[j + 1];
                const float4* p0 = reinterpret_cast<const float4*>(hin + (size_t)s0 * HIDDEN) + c;
                const float4* p1 = reinterpret_cast<const float4*>(hin + (size_t)s1 * HIDDEN) + c;
                float4 u0 = p0[0], u1 = p0[4], u2 = p0[8];
                float4 w0 = p1[0], w1 = p1[4], w2 = p1[8];
                f4add2(a0, u0, w0); f4add2(a1, u1, w1); f4add2(a2, u2, w2);
            }
            if (j < je) {
                int s0 = g_esrc[j];
                const float4* p0 = reinterpret_cast<const float4*>(hin + (size_t)s0 * HIDDEN) + c;
                f4add(a0, p0[0]); f4add(a1, p0[4]); f4add(a2, p0[8]);
            }
        }

        size_t nbase = (size_t)(node0 + n) * HIDDEN;
        const float4* px = reinterpret_cast<const float4*>(g_x0 + nbase) + c;
        float4 x0v0 = px[0], x0v1 = px[4], x0v2 = px[8];
        float4 t0, t1, t2;
        t0.x = (1.0f - ALPHA) * a0.x + ALPHA * x0v0.x;
        t0.y = (1.0f - ALPHA) * a0.y + ALPHA * x0v0.y;
        t0.z = (1.0f - ALPHA) * a0.z + ALPHA * x0v0.z;
        t0.w = (1.0f - ALPHA) * a0.w + ALPHA * x0v0.w;
        t1.x = (1.0f - ALPHA) * a1.x + ALPHA * x0v1.x;
        t1.y = (1.0f - ALPHA) * a1.y + ALPHA * x0v1.y;
        t1.z = (1.0f - ALPHA) * a1.z + ALPHA * x0v1.z;
        t1.w = (1.0f - ALPHA) * a1.w + ALPHA * x0v1.w;
        t2.x = (1.0f - ALPHA) * a2.x + ALPHA * x0v2.x;
        t2.y = (1.0f - ALPHA) * a2.y + ALPHA * x0v2.y;
        t2.z = (1.0f - ALPHA) * a2.z + ALPHA * x0v2.z;
        t2.w = (1.0f - ALPHA) * a2.w + ALPHA * x0v2.w;
        float4* pt = reinterpret_cast<float4*>(g_t + nbase) + c;
        pt[0] = t0; pt[4] = t1; pt[8] = t2;
    }
}

// ---------------------------------------------------------------------------
// GEMM (EXACT Round-8 scalar-k form): h_out = relu((1-beta)*t + beta * t@W).
// smem ~40KB -> 5 blocks/SM -> single wave.
// flip=0: write g_hb.  flip=1: write g_h.
// ---------------------------------------------------------------------------
__global__ __launch_bounds__(LTHREADS, 5)
void gemm_kernel(const float* __restrict__ convW, float beta, int flip) {
    __shared__ float sW[HIDDEN * HIDDEN];   // 9216 B
    __shared__ float sT[NPB * HIDDEN];      // 30720 B

    float* __restrict__ hout = flip ? g_h : g_hb;

    int tid = threadIdx.x;
    int node0 = blockIdx.x * NPB;
    int base = node0 * HIDDEN;

    #pragma unroll
    for (int i = tid; i < HIDDEN * HIDDEN; i += LTHREADS)
        sW[i] = convW[i];
    {
        const float4* gt4 = reinterpret_cast<const float4*>(g_t + base);
        float4* sT4w = reinterpret_cast<float4*>(sT);
        for (int i = tid; i < NPB * HIDDEN / 4; i += LTHREADS)
            sT4w[i] = gt4[i];
    }
    __syncthreads();

    int q = tid % 12;          // output quad
    int m = tid / 12;          // 0..15
    const float4* sW4 = reinterpret_cast<const float4*>(sW);
    float ob = 1.0f - beta;

    #pragma unroll
    for (int chunk = 0; chunk < 2; chunk++) {
        float4 acc[5];
        #pragma unroll
        for (int i = 0; i < 5; i++) acc[i] = make_float4(0.f, 0.f, 0.f, 0.f);

        for (int k = 0; k < HIDDEN; k++) {
            float4 w = sW4[k * 12 + q];
            #pragma unroll
            for (int i = 0; i < 5; i++) {
                float a = sT[(m + 16 * (chunk * 5 + i)) * HIDDEN + k];
                acc[i].x = fmaf(a, w.x, acc[i].x);
                acc[i].y = fmaf(a, w.y, acc[i].y);
                acc[i].z = fmaf(a, w.z, acc[i].z);
                acc[i].w = fmaf(a, w.w, acc[i].w);
            }
        }
        #pragma unroll
        for (int i = 0; i < 5; i++) {
            int n = m + 16 * (chunk * 5 + i);
            float4 t = *(reinterpret_cast<const float4*>(sT + n * HIDDEN) + q);
            float4 o;
            o.x = fmaxf(ob * t.x + beta * acc[i].x, 0.0f);
            o.y = fmaxf(ob * t.y + beta * acc[i].y, 0.0f);
            o.z = fmaxf(ob * t.z + beta * acc[i].z, 0.0f);
            o.w = fmaxf(ob * t.w + beta * acc[i].w, 0.0f);
            *(reinterpret_cast<float4*>(hout + (size_t)(node0 + n) * HIDDEN) + q) = o;
        }
    }
}

// ---------------------------------------------------------------------------
// Output (EXACT Round-8 scalar-k form): z = h @ W1 + b1 ; out = log_softmax(z)
// Z written back into sT (chunked, disjoint rows). Single wave.
// ---------------------------------------------------------------------------
__global__ __launch_bounds__(LTHREADS, 5)
void out_kernel(const float* __restrict__ W1,
                const float* __restrict__ b1,
                float* __restrict__ out) {
    __shared__ float sW[HIDDEN * HIDDEN];   // 9216 B
    __shared__ float sT[NPB * HIDDEN];      // 30720 B (h, then Z in-place)
    __shared__ float sLS[NPB];              // 640 B

    int tid = threadIdx.x;
    int node0 = blockIdx.x * NPB;
    int base = node0 * HIDDEN;

    #pragma unroll
    for (int i = tid; i < HIDDEN * HIDDEN; i += LTHREADS)
        sW[i] = W1[i];
    {
        const float4* gh4 = reinterpret_cast<const float4*>(g_h + base);
        float4* sT4w = reinterpret_cast<float4*>(sT);
        for (int i = tid; i < NPB * HIDDEN / 4; i += LTHREADS)
            sT4w[i] = gh4[i];
    }
    __syncthreads();

    int q = tid % 12;
    int m = tid / 12;
    const float4* sW4 = reinterpret_cast<const float4*>(sW);
    float4* sT4 = reinterpret_cast<float4*>(sT);
    float4 bv = reinterpret_cast<const float4*>(b1)[q];

    #pragma unroll
    for (int chunk = 0; chunk < 2; chunk++) {
        float4 acc[5];
        #pragma unroll
        for (int i = 0; i < 5; i++) acc[i] = bv;

        for (int k = 0; k < HIDDEN; k++) {
            float4 w = sW4[k * 12 + q];
            #pragma unroll
            for (int i = 0; i < 5; i++) {
                float a = sT[(m + 16 * (chunk * 5 + i)) * HIDDEN + k];
                acc[i].x = fmaf(a, w.x, acc[i].x);
                acc[i].y = fmaf(a, w.y, acc[i].y);
                acc[i].z = fmaf(a, w.z, acc[i].z);
                acc[i].w = fmaf(a, w.w, acc[i].w);
            }
        }
        __syncthreads();   // all reads of this chunk's source rows done
        #pragma unroll
        for (int i = 0; i < 5; i++) {
            int n = m + 16 * (chunk * 5 + i);
            sT4[n * 12 + q] = acc[i];
        }
    }
    __syncthreads();

    if (tid < NPB) {
        float mx = -INFINITY;
        #pragma unroll
        for (int k = 0; k < HIDDEN; k++)
            mx = fmaxf(mx, sT[tid * HIDDEN + k]);
        float s = 0.0f;
        #pragma unroll
        for (int k = 0; k < HIDDEN; k++)
            s += expf(sT[tid * HIDDEN + k] - mx);
        sLS[tid] = mx + logf(s);
    }
    __syncthreads();

    #pragma unroll
    for (int i = 0; i < 10; i++) {
        int n = m + 16 * i;
        float ls = sLS[n];
        float4 z = sT4[n * 12 + q];
        float4 o;
        o.x = z.x - ls; o.y = z.y - ls; o.z = z.z - ls; o.w = z.w - ls;
        *(reinterpret_cast<float4*>(out + (size_t)base + n * HIDDEN) + q) = o;
    }
}

// ---------------------------------------------------------------------------
extern "C" void kernel_launch(void* const* d_in, const int* in_sizes, int n_in,
                              void* d_out, int out_size) {
    const float* x     = (const float*)d_in[0];
    const int*   ei    = (const int*)  d_in[1];
    const float* W0    = (const float*)d_in[2];
    const float* b0    = (const float*)d_in[3];
    const float* convW = (const float*)d_in[4];
    const float* W1    = (const float*)d_in[5];
    const float* b1    = (const float*)d_in[6];
    float* out = (float*)d_out;

    // beta_l = log(0.5/(l+1) + 1)
    const float betas[4] = {0.4054651081f, 0.2231435513f,
                            0.1541506798f, 0.1177830357f};

    const int it = 256;
    init_kernel<<<(N_NODES * HIDDEN + it - 1) / it, it>>>(x, W0, b0, ei);

    scanA_kernel<<<SCB, 256>>>();
    scanC_kernel<<<SCB, 1024>>>();

    const int ft = 256;
    fill_kernel<<<(N_EDGES / 2 + ft - 1) / ft, ft>>>(ei);

    const int node_blocks = N_NODES / NPB;   // 625
    for (int l = 0; l < 4; l++) {
        gather_kernel<<<node_blocks, LTHREADS>>>(l & 1);
        gemm_kernel<<<node_blocks, LTHREADS>>>(convW + l * HIDDEN * HIDDEN,
                                               betas[l], l & 1);
    }

    // layers 0..3: h path g_h -> g_hb -> g_h -> g_hb -> g_h (final in g_h)
    out_kernel<<<node_blocks, LTHREADS>>>(W1, b1, out);
}

// round 12
// speedup vs baseline: 1.7508x; 1.0073x over previous
#include <cuda_runtime.h>
#include <math.h>

#define N_NODES 100000
#define N_EDGES 1600000
#define HIDDEN  48
#define ALPHA   0.1f
#define NPB     160         // nodes per block (100000 = 625 * 160)
#define LTHREADS 192        // GEMM/out: 16 m-slots x 12 quads
#define GTHREADS 256        // gather: 64 groups of 4 lanes
#define ECAP    3584        // smem edge-index buffer (mean 2560)
#define SCB     100         // scan blocks
#define SCHUNK  1000        // elements per scan block

// Scratch (__device__ globals: allocation-free rule; zero-initialized at load)
__device__ float g_x0 [N_NODES * HIDDEN];
__device__ float g_h  [N_NODES * HIDDEN];
__device__ float g_hb [N_NODES * HIDDEN];   // ping-pong buffer
__device__ float g_t  [N_NODES * HIDDEN];   // mixed pre-GEMM features
__device__ int   g_cnt[N_NODES];            // ALWAYS zero at launch entry (scanC re-zeroes)
__device__ int   g_row[N_NODES + 1];
__device__ int   g_cur[N_NODES];
__device__ int   g_esrc[N_EDGES];
__device__ int   g_part[SCB];

// ---------------------------------------------------------------------------
// Init (+fused histogram): h0 = relu(x @ W0 + b0); x0 = h0.
// g_cnt is guaranteed zero on entry (see scanC), so hist atomics fuse here.
// ---------------------------------------------------------------------------
__global__ void init_kernel(const float* __restrict__ x,
                            const float* __restrict__ W0,
                            const float* __restrict__ b0,
                            const int* __restrict__ ei) {
    int idx = blockIdx.x * blockDim.x + threadIdx.x;
    if (idx < N_EDGES)
        atomicAdd(&g_cnt[ei[N_EDGES + idx]], 1);
    if (idx >= N_NODES * HIDDEN) return;
    int n = idx / HIDDEN;
    int j = idx - n * HIDDEN;
    float v = x[n * 3 + 0] * W0[0 * HIDDEN + j]
            + x[n * 3 + 1] * W0[1 * HIDDEN + j]
            + x[n * 3 + 2] * W0[2 * HIDDEN + j]
            + b0[j];
    v = fmaxf(v, 0.0f);
    g_x0[idx] = v;
    g_h[idx]  = v;
}

// ---------------------------------------------------------------------------
// Scan A: per-block sums of g_cnt
// ---------------------------------------------------------------------------
__global__ __launch_bounds__(256) void scanA_kernel() {
    __shared__ int s[256];
    int b = blockIdx.x, t = threadIdx.x;
    int sum = 0;
    for (int i = t; i < SCHUNK; i += 256) sum += g_cnt[b * SCHUNK + i];
    s[t] = sum;
    __syncthreads();
    for (int off = 128; off > 0; off >>= 1) {
        if (t < off) s[t] += s[t + off];
        __syncthreads();
    }
    if (t == 0) g_part[b] = s[0];
}

// ---------------------------------------------------------------------------
// Scan C: final exclusive scan; also RE-ZEROES g_cnt for the next launch.
// ---------------------------------------------------------------------------
__global__ __launch_bounds__(1024) void scanC_kernel() {
    __shared__ int s[1024];
    __shared__ int sOff;
    int b = blockIdx.x, t = threadIdx.x;
    if (t == 0) sOff = 0;
    __syncthreads();
    if (t < b) atomicAdd(&sOff, g_part[t]);   // b <= 99

    int i = b * SCHUNK + t;
    int c = (t < SCHUNK) ? g_cnt[i] : 0;
    s[t] = c;
    __syncthreads();
    for (int off = 1; off < 1024; off <<= 1) {
        int v = (t >= off) ? s[t - off] : 0;
        __syncthreads();
        s[t] += v;
        __syncthreads();
    }
    int off = sOff;
    if (t < SCHUNK) {
        int excl = s[t] - c + off;
        g_row[i] = excl;
        g_cur[i] = excl;
        g_cnt[i] = 0;                          // reset for next launch/replay
    }
    if (b == SCB - 1 && t == SCHUNK - 1)
        g_row[N_NODES] = s[t] + off;
}

// ---------------------------------------------------------------------------
// CSR build: fill edge source lists (4 edges per thread, int4 loads, 4
// independent atomic chains for latency hiding)
// ---------------------------------------------------------------------------
__global__ void fill_kernel(const int* __restrict__ ei) {
    int t = blockIdx.x * blockDim.x + threadIdx.x;
    if (t >= N_EDGES / 4) return;
    int4 src = reinterpret_cast<const int4*>(ei)[t];
    int4 dst = reinterpret_cast<const int4*>(ei + N_EDGES)[t];
    int p0 = atomicAdd(&g_cur[dst.x], 1);
    int p1 = atomicAdd(&g_cur[dst.y], 1);
    int p2 = atomicAdd(&g_cur[dst.z], 1);
    int p3 = atomicAdd(&g_cur[dst.w], 1);
    g_esrc[p0] = src.x;
    g_esrc[p1] = src.y;
    g_esrc[p2] = src.z;
    g_esrc[p3] = src.w;
}

__device__ __forceinline__ void f4add(float4& a, const float4& b) {
    a.x += b.x; a.y += b.y; a.z += b.z; a.w += b.w;
}
__device__ __forceinline__ void f4add2(float4& a, const float4& b, const float4& c) {
    a.x += b.x + c.x; a.y += b.y + c.y; a.z += b.z + c.z; a.w += b.w + c.w;
}

// ---------------------------------------------------------------------------
// Gather (Round-8/11 winning form, 256 threads): 4-lane groups with
// INTERLEAVED ownership (lane c owns float4 idx {c, c+4, c+8}), dynamic node
// claiming, smem-staged indices, 2-edge unroll. 64 groups/block.
// Writes t = 0.9*agg + 0.1*x0 to g_t.
// flip=0: read g_h.  flip=1: read g_hb.
// ---------------------------------------------------------------------------
__global__ __launch_bounds__(GTHREADS)
void gather_kernel(int flip) {
    __shared__ int sE[ECAP];                // 14336 B
    __shared__ int sR[NPB + 1];             // 644 B
    __shared__ int sClaim;

    const float* __restrict__ hin = flip ? g_hb : g_h;

    int tid = threadIdx.x;
    int node0 = blockIdx.x * NPB;

    for (int i = tid; i <= NPB; i += GTHREADS)
        sR[i] = g_row[node0 + i];
    if (tid == 0) sClaim = 0;
    __syncthreads();

    int eStart = sR[0];
    int eCount = sR[NPB] - eStart;
    bool inSmem = (eCount <= ECAP);
    if (inSmem) {
        for (int i = tid; i < eCount; i += GTHREADS)
            sE[i] = g_esrc[eStart + i];
    }
    __syncthreads();

    int lane = tid & 31;
    int c = tid & 3;                          // interleave: float4 idx c, c+4, c+8
    unsigned submask = 0xFu << (lane & ~3);

    while (true) {
        int n = 0;
        if (c == 0) n = atomicAdd(&sClaim, 1);
        n = __shfl_sync(submask, n, 0, 4);
        if (n >= NPB) break;

        int rs = sR[n], re = sR[n + 1];
        float4 a0 = make_float4(0.f, 0.f, 0.f, 0.f);
        float4 a1 = a0, a2 = a0;

        if (inSmem) {
            int j = rs - eStart, je = re - eStart;
            for (; j + 2 <= je; j += 2) {
                int s0 = sE[j], s1 = sE[j + 1];
                const float4* p0 = reinterpret_cast<const float4*>(hin + (size_t)s0 * HIDDEN) + c;
                const float4* p1 = reinterpret_cast<const float4*>(hin + (size_t)s1 * HIDDEN) + c;
                float4 u0 = p0[0], u1 = p0[4], u2 = p0[8];
                float4 w0 = p1[0], w1 = p1[4], w2 = p1[8];
                f4add2(a0, u0, w0); f4add2(a1, u1, w1); f4add2(a2, u2, w2);
            }
            if (j < je) {
                int s0 = sE[j];
                const float4* p0 = reinterpret_cast<const float4*>(hin + (size_t)s0 * HIDDEN) + c;
                f4add(a0, p0[0]); f4add(a1, p0[4]); f4add(a2, p0[8]);
            }
        } else {
            int j = rs, je = re;
            for (; j + 2 <= je; j += 2) {
                int s0 = g_esrc[j], s1 = g_esrc[j + 1];
                const float4* p0 = reinterpret_cast<const float4*>(hin + (size_t)s0 * HIDDEN) + c;
                const float4* p1 = reinterpret_cast<const float4*>(hin + (size_t)s1 * HIDDEN) + c;
                float4 u0 = p0[0], u1 = p0[4], u2 = p0[8];
                float4 w0 = p1[0], w1 = p1[4], w2 = p1[8];
                f4add2(a0, u0, w0); f4add2(a1, u1, w1); f4add2(a2, u2, w2);
            }
            if (j < je) {
                int s0 = g_esrc[j];
                const float4* p0 = reinterpret_cast<const float4*>(hin + (size_t)s0 * HIDDEN) + c;
                f4add(a0, p0[0]); f4add(a1, p0[4]); f4add(a2, p0[8]);
            }
        }

        size_t nbase = (size_t)(node0 + n) * HIDDEN;
        const float4* px = reinterpret_cast<const float4*>(g_x0 + nbase) + c;
        float4 x0v0 = px[0], x0v1 = px[4], x0v2 = px[8];
        float4 t0, t1, t2;
        t0.x = (1.0f - ALPHA) * a0.x + ALPHA * x0v0.x;
        t0.y = (1.0f - ALPHA) * a0.y + ALPHA * x0v0.y;
        t0.z = (1.0f - ALPHA) * a0.z + ALPHA * x0v0.z;
        t0.w = (1.0f - ALPHA) * a0.w + ALPHA * x0v0.w;
        t1.x = (1.0f - ALPHA) * a1.x + ALPHA * x0v1.x;
        t1.y = (1.0f - ALPHA) * a1.y + ALPHA * x0v1.y;
        t1.z = (1.0f - ALPHA) * a1.z + ALPHA * x0v1.z;
        t1.w = (1.0f - ALPHA) * a1.w + ALPHA * x0v1.w;
        t2.x = (1.0f - ALPHA) * a2.x + ALPHA * x0v2.x;
        t2.y = (1.0f - ALPHA) * a2.y + ALPHA * x0v2.y;
        t2.z = (1.0f - ALPHA) * a2.z + ALPHA * x0v2.z;
        t2.w = (1.0f - ALPHA) * a2.w + ALPHA * x0v2.w;
        float4* pt = reinterpret_cast<float4*>(g_t + nbase) + c;
        pt[0] = t0; pt[4] = t1; pt[8] = t2;
    }
}

// ---------------------------------------------------------------------------
// GEMM (Round-8 scalar-k form): h_out = relu((1-beta)*t + beta * t@W).
// smem ~40KB -> 5 blocks/SM -> single wave.
// flip=0: write g_hb.  flip=1: write g_h.
// ---------------------------------------------------------------------------
__global__ __launch_bounds__(LTHREADS, 5)
void gemm_kernel(const float* __restrict__ convW, float beta, int flip) {
    __shared__ float sW[HIDDEN * HIDDEN];   // 9216 B
    __shared__ float sT[NPB * HIDDEN];      // 30720 B

    float* __restrict__ hout = flip ? g_h : g_hb;

    int tid = threadIdx.x;
    int node0 = blockIdx.x * NPB;
    int base = node0 * HIDDEN;

    #pragma unroll
    for (int i = tid; i < HIDDEN * HIDDEN; i += LTHREADS)
        sW[i] = convW[i];
    {
        const float4* gt4 = reinterpret_cast<const float4*>(g_t + base);
        float4* sT4w = reinterpret_cast<float4*>(sT);
        for (int i = tid; i < NPB * HIDDEN / 4; i += LTHREADS)
            sT4w[i] = gt4[i];
    }
    __syncthreads();

    int q = tid % 12;          // output quad
    int m = tid / 12;          // 0..15
    const float4* sW4 = reinterpret_cast<const float4*>(sW);
    float ob = 1.0f - beta;

    #pragma unroll
    for (int chunk = 0; chunk < 2; chunk++) {
        float4 acc[5];
        #pragma unroll
        for (int i = 0; i < 5; i++) acc[i] = make_float4(0.f, 0.f, 0.f, 0.f);

        for (int k = 0; k < HIDDEN; k++) {
            float4 w = sW4[k * 12 + q];
            #pragma unroll
            for (int i = 0; i < 5; i++) {
                float a = sT[(m + 16 * (chunk * 5 + i)) * HIDDEN + k];
                acc[i].x = fmaf(a, w.x, acc[i].x);
                acc[i].y = fmaf(a, w.y, acc[i].y);
                acc[i].z = fmaf(a, w.z, acc[i].z);
                acc[i].w = fmaf(a, w.w, acc[i].w);
            }
        }
        #pragma unroll
        for (int i = 0; i < 5; i++) {
            int n = m + 16 * (chunk * 5 + i);
            float4 t = *(reinterpret_cast<const float4*>(sT + n * HIDDEN) + q);
            float4 o;
            o.x = fmaxf(ob * t.x + beta * acc[i].x, 0.0f);
            o.y = fmaxf(ob * t.y + beta * acc[i].y, 0.0f);
            o.z = fmaxf(ob * t.z + beta * acc[i].z, 0.0f);
            o.w = fmaxf(ob * t.w + beta * acc[i].w, 0.0f);
            *(reinterpret_cast<float4*>(hout + (size_t)(node0 + n) * HIDDEN) + q) = o;
        }
    }
}

// ---------------------------------------------------------------------------
// Output (Round-8 scalar-k form): z = h @ W1 + b1 ; out = log_softmax(z)
// Z written back into sT (chunked, disjoint rows). Single wave.
// ---------------------------------------------------------------------------
__global__ __launch_bounds__(LTHREADS, 5)
void out_kernel(const float* __restrict__ W1,
                const float* __restrict__ b1,
                float* __restrict__ out) {
    __shared__ float sW[HIDDEN * HIDDEN];   // 9216 B
    __shared__ float sT[NPB * HIDDEN];      // 30720 B (h, then Z in-place)
    __shared__ float sLS[NPB];              // 640 B

    int tid = threadIdx.x;
    int node0 = blockIdx.x * NPB;
    int base = node0 * HIDDEN;

    #pragma unroll
    for (int i = tid; i < HIDDEN * HIDDEN; i += LTHREADS)
        sW[i] = W1[i];
    {
        const float4* gh4 = reinterpret_cast<const float4*>(g_h + base);
        float4* sT4w = reinterpret_cast<float4*>(sT);
        for (int i = tid; i < NPB * HIDDEN / 4; i += LTHREADS)
            sT4w[i] = gh4[i];
    }
    __syncthreads();

    int q = tid % 12;
    int m = tid / 12;
    const float4* sW4 = reinterpret_cast<const float4*>(sW);
    float4* sT4 = reinterpret_cast<float4*>(sT);
    float4 bv = reinterpret_cast<const float4*>(b1)[q];

    #pragma unroll
    for (int chunk = 0; chunk < 2; chunk++) {
        float4 acc[5];
        #pragma unroll
        for (int i = 0; i < 5; i++) acc[i] = bv;

        for (int k = 0; k < HIDDEN; k++) {
            float4 w = sW4[k * 12 + q];
            #pragma unroll
            for (int i = 0; i < 5; i++) {
                float a = sT[(m + 16 * (chunk * 5 + i)) * HIDDEN + k];
                acc[i].x = fmaf(a, w.x, acc[i].x);
                acc[i].y = fmaf(a, w.y, acc[i].y);
                acc[i].z = fmaf(a, w.z, acc[i].z);
                acc[i].w = fmaf(a, w.w, acc[i].w);
            }
        }
        __syncthreads();   // all reads of this chunk's source rows done
        #pragma unroll
        for (int i = 0; i < 5; i++) {
            int n = m + 16 * (chunk * 5 + i);
            sT4[n * 12 + q] = acc[i];
        }
    }
    __syncthreads();

    if (tid < NPB) {
        float mx = -INFINITY;
        #pragma unroll
        for (int k = 0; k < HIDDEN; k++)
            mx = fmaxf(mx, sT[tid * HIDDEN + k]);
        float s = 0.0f;
        #pragma unroll
        for (int k = 0; k < HIDDEN; k++)
            s += expf(sT[tid * HIDDEN + k] - mx);
        sLS[tid] = mx + logf(s);
    }
    __syncthreads();

    #pragma unroll
    for (int i = 0; i < 10; i++) {
        int n = m + 16 * i;
        float ls = sLS[n];
        float4 z = sT4[n * 12 + q];
        float4 o;
        o.x = z.x - ls; o.y = z.y - ls; o.z = z.z - ls; o.w = z.w - ls;
        *(reinterpret_cast<float4*>(out + (size_t)base + n * HIDDEN) + q) = o;
    }
}

// ---------------------------------------------------------------------------
extern "C" void kernel_launch(void* const* d_in, const int* in_sizes, int n_in,
                              void* d_out, int out_size) {
    const float* x     = (const float*)d_in[0];
    const int*   ei    = (const int*)  d_in[1];
    const float* W0    = (const float*)d_in[2];
    const float* b0    = (const float*)d_in[3];
    const float* convW = (const float*)d_in[4];
    const float* W1    = (const float*)d_in[5];
    const float* b1    = (const float*)d_in[6];
    float* out = (float*)d_out;

    // beta_l = log(0.5/(l+1) + 1)
    const float betas[4] = {0.4054651081f, 0.2231435513f,
                            0.1541506798f, 0.1177830357f};

    const int it = 256;
    init_kernel<<<(N_NODES * HIDDEN + it - 1) / it, it>>>(x, W0, b0, ei);

    scanA_kernel<<<SCB, 256>>>();
    scanC_kernel<<<SCB, 1024>>>();

    const int ft = 256;
    fill_kernel<<<(N_EDGES / 4 + ft - 1) / ft, ft>>>(ei);

    const int node_blocks = N_NODES / NPB;   // 625
    for (int l = 0; l < 4; l++) {
        gather_kernel<<<node_blocks, GTHREADS>>>(l & 1);
        gemm_kernel<<<node_blocks, LTHREADS>>>(convW + l * HIDDEN * HIDDEN,
                                               betas[l], l & 1);
    }

    // layers 0..3: h path g_h -> g_hb -> g_h -> g_hb -> g_h (final in g_h)
    out_kernel<<<node_blocks, LTHREADS>>>(W1, b1, out);
}

// round 13
// speedup vs baseline: 1.7731x; 1.0128x over previous
#include <cuda_runtime.h>
#include <math.h>

#define N_NODES 100000
#define N_EDGES 1600000
#define HIDDEN  48
#define ALPHA   0.1f
#define NPB     80          // nodes per block, gather/gemm (100000 = 1250 * 80)
#define ONPB    160         // nodes per block, out kernel (100000 = 625 * 160)
#define LTHREADS 192        // gemm/out: 16 m-slots x 12 quads
#define GTHREADS 256        // gather: 64 groups of 4 lanes
#define ECAP    1792        // smem edge-index buffer (mean 1280, +14 sigma)
#define SCB     100         // scan blocks
#define SCHUNK  1000        // elements per scan block

// Scratch (__device__ globals: allocation-free rule; zero-initialized at load)
__device__ float g_x0 [N_NODES * HIDDEN];
__device__ float g_h  [N_NODES * HIDDEN];
__device__ float g_hb [N_NODES * HIDDEN];   // ping-pong buffer
__device__ float g_t  [N_NODES * HIDDEN];   // mixed pre-GEMM features
__device__ int   g_cnt[N_NODES];            // ALWAYS zero at launch entry (scanC re-zeroes)
__device__ int   g_row[N_NODES + 1];
__device__ int   g_cur[N_NODES];
__device__ int   g_esrc[N_EDGES];
__device__ int   g_part[SCB];

// ---------------------------------------------------------------------------
// Init (+fused histogram), vectorized: one thread per node-quad.
// h0 = relu(x @ W0 + b0); x0 = h0. g_cnt is zero on entry (scanC re-zeroes).
// ---------------------------------------------------------------------------
__global__ void init_kernel(const float* __restrict__ x,
                            const float* __restrict__ W0,
                            const float* __restrict__ b0,
                            const int* __restrict__ ei) {
    int idx = blockIdx.x * blockDim.x + threadIdx.x;
    if (idx < N_EDGES)
        atomicAdd(&g_cnt[ei[N_EDGES + idx]], 1);
    if (idx >= N_NODES * 12) return;
    int n = idx / 12;
    int q = idx - n * 12;
    float x0v = x[n * 3 + 0], x1v = x[n * 3 + 1], x2v = x[n * 3 + 2];
    const float4* W04 = reinterpret_cast<const float4*>(W0);
    float4 w0 = W04[0 * 12 + q];
    float4 w1 = W04[1 * 12 + q];
    float4 w2 = W04[2 * 12 + q];
    float4 b  = reinterpret_cast<const float4*>(b0)[q];
    float4 v;
    v.x = fmaxf(fmaf(x0v, w0.x, fmaf(x1v, w1.x, fmaf(x2v, w2.x, b.x))), 0.0f);
    v.y = fmaxf(fmaf(x0v, w0.y, fmaf(x1v, w1.y, fmaf(x2v, w2.y, b.y))), 0.0f);
    v.z = fmaxf(fmaf(x0v, w0.z, fmaf(x1v, w1.z, fmaf(x2v, w2.z, b.z))), 0.0f);
    v.w = fmaxf(fmaf(x0v, w0.w, fmaf(x1v, w1.w, fmaf(x2v, w2.w, b.w))), 0.0f);
    reinterpret_cast<float4*>(g_x0)[idx] = v;
    reinterpret_cast<float4*>(g_h)[idx]  = v;
}

// ---------------------------------------------------------------------------
// Scan A: per-block sums of g_cnt
// ---------------------------------------------------------------------------
__global__ __launch_bounds__(256) void scanA_kernel() {
    __shared__ int s[256];
    int b = blockIdx.x, t = threadIdx.x;
    int sum = 0;
    for (int i = t; i < SCHUNK; i += 256) sum += g_cnt[b * SCHUNK + i];
    s[t] = sum;
    __syncthreads();
    for (int off = 128; off > 0; off >>= 1) {
        if (t < off) s[t] += s[t + off];
        __syncthreads();
    }
    if (t == 0) g_part[b] = s[0];
}

// ---------------------------------------------------------------------------
// Scan C: final exclusive scan; also RE-ZEROES g_cnt for the next launch.
// ---------------------------------------------------------------------------
__global__ __launch_bounds__(1024) void scanC_kernel() {
    __shared__ int s[1024];
    __shared__ int sOff;
    int b = blockIdx.x, t = threadIdx.x;
    if (t == 0) sOff = 0;
    __syncthreads();
    if (t < b) atomicAdd(&sOff, g_part[t]);   // b <= 99

    int i = b * SCHUNK + t;
    int c = (t < SCHUNK) ? g_cnt[i] : 0;
    s[t] = c;
    __syncthreads();
    for (int off = 1; off < 1024; off <<= 1) {
        int v = (t >= off) ? s[t - off] : 0;
        __syncthreads();
        s[t] += v;
        __syncthreads();
    }
    int off = sOff;
    if (t < SCHUNK) {
        int excl = s[t] - c + off;
        g_row[i] = excl;
        g_cur[i] = excl;
        g_cnt[i] = 0;                          // reset for next launch/replay
    }
    if (b == SCB - 1 && t == SCHUNK - 1)
        g_row[N_NODES] = s[t] + off;
}

// ---------------------------------------------------------------------------
// CSR build: fill edge source lists (4 edges per thread, int4 loads)
// ---------------------------------------------------------------------------
__global__ void fill_kernel(const int* __restrict__ ei) {
    int t = blockIdx.x * blockDim.x + threadIdx.x;
    if (t >= N_EDGES / 4) return;
    int4 src = reinterpret_cast<const int4*>(ei)[t];
    int4 dst = reinterpret_cast<const int4*>(ei + N_EDGES)[t];
    int p0 = atomicAdd(&g_cur[dst.x], 1);
    int p1 = atomicAdd(&g_cur[dst.y], 1);
    int p2 = atomicAdd(&g_cur[dst.z], 1);
    int p3 = atomicAdd(&g_cur[dst.w], 1);
    g_esrc[p0] = src.x;
    g_esrc[p1] = src.y;
    g_esrc[p2] = src.z;
    g_esrc[p3] = src.w;
}

__device__ __forceinline__ void f4add(float4& a, const float4& b) {
    a.x += b.x; a.y += b.y; a.z += b.z; a.w += b.w;
}
__device__ __forceinline__ void f4add2(float4& a, const float4& b, const float4& c) {
    a.x += b.x + c.x; a.y += b.y + c.y; a.z += b.z + c.z; a.w += b.w + c.w;
}

// ---------------------------------------------------------------------------
// Gather: 4-lane groups, interleaved ownership (lane c owns float4 idx
// {c, c+4, c+8}), dynamic node claiming, smem-staged indices, 2-edge unroll.
// NPB=80 -> 1250 blocks -> fine-grained SM load balance.
// Writes t = 0.9*agg + 0.1*x0 to g_t.
// flip=0: read g_h.  flip=1: read g_hb.
// ---------------------------------------------------------------------------
__global__ __launch_bounds__(GTHREADS)
void gather_kernel(int flip) {
    __shared__ int sE[ECAP];                // 7168 B
    __shared__ int sR[NPB + 1];             // 324 B
    __shared__ int sClaim;

    const float* __restrict__ hin = flip ? g_hb : g_h;

    int tid = threadIdx.x;
    int node0 = blockIdx.x * NPB;

    for (int i = tid; i <= NPB; i += GTHREADS)
        sR[i] = g_row[node0 + i];
    if (tid == 0) sClaim = 0;
    __syncthreads();

    int eStart = sR[0];
    int eCount = sR[NPB] - eStart;
    bool inSmem = (eCount <= ECAP);
    if (inSmem) {
        for (int i = tid; i < eCount; i += GTHREADS)
            sE[i] = g_esrc[eStart + i];
    }
    __syncthreads();

    int lane = tid & 31;
    int c = tid & 3;                          // interleave: float4 idx c, c+4, c+8
    unsigned submask = 0xFu << (lane & ~3);

    while (true) {
        int n = 0;
        if (c == 0) n = atomicAdd(&sClaim, 1);
        n = __shfl_sync(submask, n, 0, 4);
        if (n >= NPB) break;

        int rs = sR[n], re = sR[n + 1];
        float4 a0 = make_float4(0.f, 0.f, 0.f, 0.f);
        float4 a1 = a0, a2 = a0;

        if (inSmem) {
            int j = rs - eStart, je = re - eStart;
            for (; j + 2 <= je; j += 2) {
                int s0 = sE[j], s1 = sE[j + 1];
                const float4* p0 = reinterpret_cast<const float4*>(hin + (size_t)s0 * HIDDEN) + c;
                const float4* p1 = reinterpret_cast<const float4*>(hin + (size_t)s1 * HIDDEN) + c;
                float4 u0 = p0[0], u1 = p0[4], u2 = p0[8];
                float4 w0 = p1[0], w1 = p1[4], w2 = p1[8];
                f4add2(a0, u0, w0); f4add2(a1, u1, w1); f4add2(a2, u2, w2);
            }
            if (j < je) {
                int s0 = sE[j];
                const float4* p0 = reinterpret_cast<const float4*>(hin + (size_t)s0 * HIDDEN) + c;
                f4add(a0, p0[0]); f4add(a1, p0[4]); f4add(a2, p0[8]);
            }
        } else {
            int j = rs, je = re;
            for (; j + 2 <= je; j += 2) {
                int s0 = g_esrc[j], s1 = g_esrc[j + 1];
                const float4* p0 = reinterpret_cast<const float4*>(hin + (size_t)s0 * HIDDEN) + c;
                const float4* p1 = reinterpret_cast<const float4*>(hin + (size_t)s1 * HIDDEN) + c;
                float4 u0 = p0[0], u1 = p0[4], u2 = p0[8];
                float4 w0 = p1[0], w1 = p1[4], w2 = p1[8];
                f4add2(a0, u0, w0); f4add2(a1, u1, w1); f4add2(a2, u2, w2);
            }
            if (j < je) {
                int s0 = g_esrc[j];
                const float4* p0 = reinterpret_cast<const float4*>(hin + (size_t)s0 * HIDDEN) + c;
                f4add(a0, p0[0]); f4add(a1, p0[4]); f4add(a2, p0[8]);
            }
        }

        size_t nbase = (size_t)(node0 + n) * HIDDEN;
        const float4* px = reinterpret_cast<const float4*>(g_x0 + nbase) + c;
        float4 x0v0 = px[0], x0v1 = px[4], x0v2 = px[8];
        float4 t0, t1, t2;
        t0.x = (1.0f - ALPHA) * a0.x + ALPHA * x0v0.x;
        t0.y = (1.0f - ALPHA) * a0.y + ALPHA * x0v0.y;
        t0.z = (1.0f - ALPHA) * a0.z + ALPHA * x0v0.z;
        t0.w = (1.0f - ALPHA) * a0.w + ALPHA * x0v0.w;
        t1.x = (1.0f - ALPHA) * a1.x + ALPHA * x0v1.x;
        t1.y = (1.0f - ALPHA) * a1.y + ALPHA * x0v1.y;
        t1.z = (1.0f - ALPHA) * a1.z + ALPHA * x0v1.z;
        t1.w = (1.0f - ALPHA) * a1.w + ALPHA * x0v1.w;
        t2.x = (1.0f - ALPHA) * a2.x + ALPHA * x0v2.x;
        t2.y = (1.0f - ALPHA) * a2.y + ALPHA * x0v2.y;
        t2.z = (1.0f - ALPHA) * a2.z + ALPHA * x0v2.z;
        t2.w = (1.0f - ALPHA) * a2.w + ALPHA * x0v2.w;
        float4* pt = reinterpret_cast<float4*>(g_t + nbase) + c;
        pt[0] = t0; pt[4] = t1; pt[8] = t2;
    }
}

// ---------------------------------------------------------------------------
// GEMM (scalar-k, proven spill-free at 68-reg budget):
// h_out = relu((1-beta)*t + beta * t@W). NPB=80 -> single 5-node chunk.
// flip=0: write g_hb.  flip=1: write g_h.
// ---------------------------------------------------------------------------
__global__ __launch_bounds__(LTHREADS, 5)
void gemm_kernel(const float* __restrict__ convW, float beta, int flip) {
    __shared__ float sW[HIDDEN * HIDDEN];   // 9216 B
    __shared__ float sT[NPB * HIDDEN];      // 15360 B

    float* __restrict__ hout = flip ? g_h : g_hb;

    int tid = threadIdx.x;
    int node0 = blockIdx.x * NPB;
    int base = node0 * HIDDEN;

    #pragma unroll
    for (int i = tid; i < HIDDEN * HIDDEN; i += LTHREADS)
        sW[i] = convW[i];
    {
        const float4* gt4 = reinterpret_cast<const float4*>(g_t + base);
        float4* sT4w = reinterpret_cast<float4*>(sT);
        for (int i = tid; i < NPB * HIDDEN / 4; i += LTHREADS)
            sT4w[i] = gt4[i];
    }
    __syncthreads();

    int q = tid % 12;          // output quad
    int m = tid / 12;          // 0..15
    const float4* sW4 = reinterpret_cast<const float4*>(sW);
    float ob = 1.0f - beta;

    float4 acc[5];
    #pragma unroll
    for (int i = 0; i < 5; i++) acc[i] = make_float4(0.f, 0.f, 0.f, 0.f);

    for (int k = 0; k < HIDDEN; k++) {
        float4 w = sW4[k * 12 + q];
        #pragma unroll
        for (int i = 0; i < 5; i++) {
            float a = sT[(m + 16 * i) * HIDDEN + k];
            acc[i].x = fmaf(a, w.x, acc[i].x);
            acc[i].y = fmaf(a, w.y, acc[i].y);
            acc[i].z = fmaf(a, w.z, acc[i].z);
            acc[i].w = fmaf(a, w.w, acc[i].w);
        }
    }
    #pragma unroll
    for (int i = 0; i < 5; i++) {
        int n = m + 16 * i;
        float4 t = *(reinterpret_cast<const float4*>(sT + n * HIDDEN) + q);
        float4 o;
        o.x = fmaxf(ob * t.x + beta * acc[i].x, 0.0f);
        o.y = fmaxf(ob * t.y + beta * acc[i].y, 0.0f);
        o.z = fmaxf(ob * t.z + beta * acc[i].z, 0.0f);
        o.w = fmaxf(ob * t.w + beta * acc[i].w, 0.0f);
        *(reinterpret_cast<float4*>(hout + (size_t)(node0 + n) * HIDDEN) + q) = o;
    }
}

// ---------------------------------------------------------------------------
// Output (scalar-k): z = h @ W1 + b1 ; out = log_softmax(z)   (reads g_h)
// ONPB=160; Z written back into sT (chunked, disjoint rows). Single wave.
// ---------------------------------------------------------------------------
__global__ __launch_bounds__(LTHREADS, 5)
void out_kernel(const float* __restrict__ W1,
                const float* __restrict__ b1,
                float* __restrict__ out) {
    __shared__ float sW[HIDDEN * HIDDEN];   // 9216 B
    __shared__ float sT[ONPB * HIDDEN];     // 30720 B (h, then Z in-place)
    __shared__ float sLS[ONPB];             // 640 B

    int tid = threadIdx.x;
    int node0 = blockIdx.x * ONPB;
    int base = node0 * HIDDEN;

    #pragma unroll
    for (int i = tid; i < HIDDEN * HIDDEN; i += LTHREADS)
        sW[i] = W1[i];
    {
        const float4* gh4 = reinterpret_cast<const float4*>(g_h + base);
        float4* sT4w = reinterpret_cast<float4*>(sT);
        for (int i = tid; i < ONPB * HIDDEN / 4; i += LTHREADS)
            sT4w[i] = gh4[i];
    }
    __syncthreads();

    int q = tid % 12;
    int m = tid / 12;
    const float4* sW4 = reinterpret_cast<const float4*>(sW);
    float4* sT4 = reinterpret_cast<float4*>(sT);
    float4 bv = reinterpret_cast<const float4*>(b1)[q];

    #pragma unroll
    for (int chunk = 0; chunk < 2; chunk++) {
        float4 acc[5];
        #pragma unroll
        for (int i = 0; i < 5; i++) acc[i] = bv;

        for (int k = 0; k < HIDDEN; k++) {
            float4 w = sW4[k * 12 + q];
            #pragma unroll
            for (int i = 0; i < 5; i++) {
                float a = sT[(m + 16 * (chunk * 5 + i)) * HIDDEN + k];
                acc[i].x = fmaf(a, w.x, acc[i].x);
                acc[i].y = fmaf(a, w.y, acc[i].y);
                acc[i].z = fmaf(a, w.z, acc[i].z);
                acc[i].w = fmaf(a, w.w, acc[i].w);
            }
        }
        __syncthreads();   // all reads of this chunk's source rows done
        #pragma unroll
        for (int i = 0; i < 5; i++) {
            int n = m + 16 * (chunk * 5 + i);
            sT4[n * 12 + q] = acc[i];
        }
    }
    __syncthreads();

    if (tid < ONPB) {
        float mx = -INFINITY;
        #pragma unroll
        for (int k = 0; k < HIDDEN; k++)
            mx = fmaxf(mx, sT[tid * HIDDEN + k]);
        float s = 0.0f;
        #pragma unroll
        for (int k = 0; k < HIDDEN; k++)
            s += expf(sT[tid * HIDDEN + k] - mx);
        sLS[tid] = mx + logf(s);
    }
    __syncthreads();

    #pragma unroll
    for (int i = 0; i < 10; i++) {
        int n = m + 16 * i;
        float ls = sLS[n];
        float4 z = sT4[n * 12 + q];
        float4 o;
        o.x = z.x - ls; o.y = z.y - ls; o.z = z.z - ls; o.w = z.w - ls;
        *(reinterpret_cast<float4*>(out + (size_t)base + n * HIDDEN) + q) = o;
    }
}

// ---------------------------------------------------------------------------
extern "C" void kernel_launch(void* const* d_in, const int* in_sizes, int n_in,
                              void* d_out, int out_size) {
    const float* x     = (const float*)d_in[0];
    const int*   ei    = (const int*)  d_in[1];
    const float* W0    = (const float*)d_in[2];
    const float* b0    = (const float*)d_in[3];
    const float* convW = (const float*)d_in[4];
    const float* W1    = (const float*)d_in[5];
    const float* b1    = (const float*)d_in[6];
    float* out = (float*)d_out;

    // beta_l = log(0.5/(l+1) + 1)
    const float betas[4] = {0.4054651081f, 0.2231435513f,
                            0.1541506798f, 0.1177830357f};

    const int it = 256;
    init_kernel<<<(N_EDGES + it - 1) / it, it>>>(x, W0, b0, ei);

    scanA_kernel<<<SCB, 256>>>();
    scanC_kernel<<<SCB, 1024>>>();

    const int ft = 256;
    fill_kernel<<<(N_EDGES / 4 + ft - 1) / ft, ft>>>(ei);

    const int node_blocks = N_NODES / NPB;   // 1250
    for (int l = 0; l < 4; l++) {
        gather_kernel<<<node_blocks, GTHREADS>>>(l & 1);
        gemm_kernel<<<node_blocks, LTHREADS>>>(convW + l * HIDDEN * HIDDEN,
                                               betas[l], l & 1);
    }

    // layers 0..3: h path g_h -> g_hb -> g_h -> g_hb -> g_h (final in g_h)
    out_kernel<<<N_NODES / ONPB, LTHREADS>>>(W1, b1, out);
}

// round 14
// speedup vs baseline: 2.1663x; 1.2218x over previous
#include <cuda_runtime.h>
#include <math.h>

#define N_NODES 100000
#define N_EDGES 1600000
#define HIDDEN  48
#define ALPHA   0.1f
#define NPB     80          // nodes per block, layer kernel (100000 = 1250 * 80)
#define ONPB    160         // nodes per block, out kernel (100000 = 625 * 160)
#define LTHREADS 192        // out: 16 m-slots x 12 quads
#define FTHREADS 256        // layer: 64 gather groups of 4; gemm uses 240
#define ECAP    1792        // smem edge-index buffer (mean 1280)
#define SCB     100         // scan blocks
#define SCHUNK  1000        // elements per scan block

// Scratch (__device__ globals: allocation-free rule; zero-initialized at load)
__device__ float g_x0 [N_NODES * HIDDEN];
__device__ float g_h  [N_NODES * HIDDEN];
__device__ float g_hb [N_NODES * HIDDEN];   // ping-pong buffer
__device__ int   g_cnt[N_NODES];            // ALWAYS zero at launch entry (scanC re-zeroes)
__device__ int   g_row[N_NODES + 1];
__device__ int   g_cur[N_NODES];
__device__ int   g_esrc[N_EDGES];
__device__ int   g_part[SCB];

// ---------------------------------------------------------------------------
// Init (+fused histogram), vectorized: one thread per node-quad.
// ---------------------------------------------------------------------------
__global__ void init_kernel(const float* __restrict__ x,
                            const float* __restrict__ W0,
                            const float* __restrict__ b0,
                            const int* __restrict__ ei) {
    int idx = blockIdx.x * blockDim.x + threadIdx.x;
    if (idx < N_EDGES)
        atomicAdd(&g_cnt[ei[N_EDGES + idx]], 1);
    if (idx >= N_NODES * 12) return;
    int n = idx / 12;
    int q = idx - n * 12;
    float x0v = x[n * 3 + 0], x1v = x[n * 3 + 1], x2v = x[n * 3 + 2];
    const float4* W04 = reinterpret_cast<const float4*>(W0);
    float4 w0 = W04[0 * 12 + q];
    float4 w1 = W04[1 * 12 + q];
    float4 w2 = W04[2 * 12 + q];
    float4 b  = reinterpret_cast<const float4*>(b0)[q];
    float4 v;
    v.x = fmaxf(fmaf(x0v, w0.x, fmaf(x1v, w1.x, fmaf(x2v, w2.x, b.x))), 0.0f);
    v.y = fmaxf(fmaf(x0v, w0.y, fmaf(x1v, w1.y, fmaf(x2v, w2.y, b.y))), 0.0f);
    v.z = fmaxf(fmaf(x0v, w0.z, fmaf(x1v, w1.z, fmaf(x2v, w2.z, b.z))), 0.0f);
    v.w = fmaxf(fmaf(x0v, w0.w, fmaf(x1v, w1.w, fmaf(x2v, w2.w, b.w))), 0.0f);
    reinterpret_cast<float4*>(g_x0)[idx] = v;
    reinterpret_cast<float4*>(g_h)[idx]  = v;
}

// ---------------------------------------------------------------------------
// Scan A: per-block sums of g_cnt
// ---------------------------------------------------------------------------
__global__ __launch_bounds__(256) void scanA_kernel() {
    __shared__ int s[256];
    int b = blockIdx.x, t = threadIdx.x;
    int sum = 0;
    for (int i = t; i < SCHUNK; i += 256) sum += g_cnt[b * SCHUNK + i];
    s[t] = sum;
    __syncthreads();
    for (int off = 128; off > 0; off >>= 1) {
        if (t < off) s[t] += s[t + off];
        __syncthreads();
    }
    if (t == 0) g_part[b] = s[0];
}

// ---------------------------------------------------------------------------
// Scan C: final exclusive scan; also RE-ZEROES g_cnt for the next launch.
// ---------------------------------------------------------------------------
__global__ __launch_bounds__(1024) void scanC_kernel() {
    __shared__ int s[1024];
    __shared__ int sOff;
    int b = blockIdx.x, t = threadIdx.x;
    if (t == 0) sOff = 0;
    __syncthreads();
    if (t < b) atomicAdd(&sOff, g_part[t]);   // b <= 99

    int i = b * SCHUNK + t;
    int c = (t < SCHUNK) ? g_cnt[i] : 0;
    s[t] = c;
    __syncthreads();
    for (int off = 1; off < 1024; off <<= 1) {
        int v = (t >= off) ? s[t - off] : 0;
        __syncthreads();
        s[t] += v;
        __syncthreads();
    }
    int off = sOff;
    if (t < SCHUNK) {
        int excl = s[t] - c + off;
        g_row[i] = excl;
        g_cur[i] = excl;
        g_cnt[i] = 0;                          // reset for next launch/replay
    }
    if (b == SCB - 1 && t == SCHUNK - 1)
        g_row[N_NODES] = s[t] + off;
}

// ---------------------------------------------------------------------------
// CSR build: fill edge source lists (4 edges per thread, int4 loads)
// ---------------------------------------------------------------------------
__global__ void fill_kernel(const int* __restrict__ ei) {
    int t = blockIdx.x * blockDim.x + threadIdx.x;
    if (t >= N_EDGES / 4) return;
    int4 src = reinterpret_cast<const int4*>(ei)[t];
    int4 dst = reinterpret_cast<const int4*>(ei + N_EDGES)[t];
    int p0 = atomicAdd(&g_cur[dst.x], 1);
    int p1 = atomicAdd(&g_cur[dst.y], 1);
    int p2 = atomicAdd(&g_cur[dst.z], 1);
    int p3 = atomicAdd(&g_cur[dst.w], 1);
    g_esrc[p0] = src.x;
    g_esrc[p1] = src.y;
    g_esrc[p2] = src.z;
    g_esrc[p3] = src.w;
}

__device__ __forceinline__ void f4add(float4& a, const float4& b) {
    a.x += b.x; a.y += b.y; a.z += b.z; a.w += b.w;
}
__device__ __forceinline__ void f4add2(float4& a, const float4& b, const float4& c) {
    a.x += b.x + c.x; a.y += b.y + c.y; a.z += b.z + c.z; a.w += b.w + c.w;
}

// ---------------------------------------------------------------------------
// Fused layer: gather (4-lane interleaved groups, dynamic claiming, smem
// indices, 2-edge unroll) -> sT in smem -> scalar-k GEMM -> relu -> hout.
// Eliminates the g_t global round-trip (38.4 MB/layer of L2 traffic).
// NPB=80, 1250 small blocks -> wave tail ~1 block-time only.
// flip=0: read g_h, write g_hb.  flip=1: read g_hb, write g_h.
// ---------------------------------------------------------------------------
__global__ __launch_bounds__(FTHREADS)
void layer_kernel(const float* __restrict__ convW, float beta, int flip) {
    __shared__ float sW[HIDDEN * HIDDEN];   // 9216 B
    __shared__ float sT[NPB * HIDDEN];      // 15360 B
    __shared__ int   sE[ECAP];              // 7168 B
    __shared__ int   sR[NPB + 1];           // 324 B
    __shared__ int   sClaim;

    const float* __restrict__ hin  = flip ? g_hb : g_h;
    float*       __restrict__ hout = flip ? g_h  : g_hb;

    int tid = threadIdx.x;
    int node0 = blockIdx.x * NPB;

    #pragma unroll
    for (int i = tid; i < HIDDEN * HIDDEN; i += FTHREADS)
        sW[i] = convW[i];
    for (int i = tid; i <= NPB; i += FTHREADS)
        sR[i] = g_row[node0 + i];
    if (tid == 0) sClaim = 0;
    __syncthreads();

    int eStart = sR[0];
    int eCount = sR[NPB] - eStart;
    bool inSmem = (eCount <= ECAP);
    if (inSmem) {
        for (int i = tid; i < eCount; i += FTHREADS)
            sE[i] = g_esrc[eStart + i];
        __syncthreads();
    }

    int lane = tid & 31;
    int c = tid & 3;                          // interleave: float4 idx c, c+4, c+8
    unsigned submask = 0xFu << (lane & ~3);

    while (true) {
        int n = 0;
        if (c == 0) n = atomicAdd(&sClaim, 1);
        n = __shfl_sync(submask, n, 0, 4);
        if (n >= NPB) break;

        int rs = sR[n], re = sR[n + 1];
        float4 a0 = make_float4(0.f, 0.f, 0.f, 0.f);
        float4 a1 = a0, a2 = a0;

        if (inSmem) {
            int j = rs - eStart, je = re - eStart;
            for (; j + 2 <= je; j += 2) {
                int s0 = sE[j], s1 = sE[j + 1];
                const float4* p0 = reinterpret_cast<const float4*>(hin + (size_t)s0 * HIDDEN) + c;
                const float4* p1 = reinterpret_cast<const float4*>(hin + (size_t)s1 * HIDDEN) + c;
                float4 u0 = p0[0], u1 = p0[4], u2 = p0[8];
                float4 w0 = p1[0], w1 = p1[4], w2 = p1[8];
                f4add2(a0, u0, w0); f4add2(a1, u1, w1); f4add2(a2, u2, w2);
            }
            if (j < je) {
                int s0 = sE[j];
                const float4* p0 = reinterpret_cast<const float4*>(hin + (size_t)s0 * HIDDEN) + c;
                f4add(a0, p0[0]); f4add(a1, p0[4]); f4add(a2, p0[8]);
            }
        } else {
            int j = rs, je = re;
            for (; j + 2 <= je; j += 2) {
                int s0 = g_esrc[j], s1 = g_esrc[j + 1];
                const float4* p0 = reinterpret_cast<const float4*>(hin + (size_t)s0 * HIDDEN) + c;
                const float4* p1 = reinterpret_cast<const float4*>(hin + (size_t)s1 * HIDDEN) + c;
                float4 u0 = p0[0], u1 = p0[4], u2 = p0[8];
                float4 w0 = p1[0], w1 = p1[4], w2 = p1[8];
                f4add2(a0, u0, w0); f4add2(a1, u1, w1); f4add2(a2, u2, w2);
            }
            if (j < je) {
                int s0 = g_esrc[j];
                const float4* p0 = reinterpret_cast<const float4*>(hin + (size_t)s0 * HIDDEN) + c;
                f4add(a0, p0[0]); f4add(a1, p0[4]); f4add(a2, p0[8]);
            }
        }

        size_t nbase = (size_t)(node0 + n) * HIDDEN;
        const float4* px = reinterpret_cast<const float4*>(g_x0 + nbase) + c;
        float4 x0v0 = px[0], x0v1 = px[4], x0v2 = px[8];
        float4 t0, t1, t2;
        t0.x = (1.0f - ALPHA) * a0.x + ALPHA * x0v0.x;
        t0.y = (1.0f - ALPHA) * a0.y + ALPHA * x0v0.y;
        t0.z = (1.0f - ALPHA) * a0.z + ALPHA * x0v0.z;
        t0.w = (1.0f - ALPHA) * a0.w + ALPHA * x0v0.w;
        t1.x = (1.0f - ALPHA) * a1.x + ALPHA * x0v1.x;
        t1.y = (1.0f - ALPHA) * a1.y + ALPHA * x0v1.y;
        t1.z = (1.0f - ALPHA) * a1.z + ALPHA * x0v1.z;
        t1.w = (1.0f - ALPHA) * a1.w + ALPHA * x0v1.w;
        t2.x = (1.0f - ALPHA) * a2.x + ALPHA * x0v2.x;
        t2.y = (1.0f - ALPHA) * a2.y + ALPHA * x0v2.y;
        t2.z = (1.0f - ALPHA) * a2.z + ALPHA * x0v2.z;
        t2.w = (1.0f - ALPHA) * a2.w + ALPHA * x0v2.w;
        float4* pt = reinterpret_cast<float4*>(sT + n * HIDDEN) + c;
        pt[0] = t0; pt[4] = t1; pt[8] = t2;
    }
    __syncthreads();

    // --- scalar-k GEMM: 240 threads, thread (q, m) does quad q of 4 nodes ---
    if (tid < 240) {
        int q = tid % 12;          // output quad
        int m = tid / 12;          // 0..19; nodes m, m+20, m+40, m+60
        const float4* sW4 = reinterpret_cast<const float4*>(sW);
        float ob = 1.0f - beta;

        float4 acc[4];
        #pragma unroll
        for (int i = 0; i < 4; i++) acc[i] = make_float4(0.f, 0.f, 0.f, 0.f);

        for (int k = 0; k < HIDDEN; k++) {
            float4 w = sW4[k * 12 + q];
            #pragma unroll
            for (int i = 0; i < 4; i++) {
                float a = sT[(m + 20 * i) * HIDDEN + k];
                acc[i].x = fmaf(a, w.x, acc[i].x);
                acc[i].y = fmaf(a, w.y, acc[i].y);
                acc[i].z = fmaf(a, w.z, acc[i].z);
                acc[i].w = fmaf(a, w.w, acc[i].w);
            }
        }
        #pragma unroll
        for (int i = 0; i < 4; i++) {
            int n = m + 20 * i;
            float4 t = *(reinterpret_cast<const float4*>(sT + n * HIDDEN) + q);
            float4 o;
            o.x = fmaxf(ob * t.x + beta * acc[i].x, 0.0f);
            o.y = fmaxf(ob * t.y + beta * acc[i].y, 0.0f);
            o.z = fmaxf(ob * t.z + beta * acc[i].z, 0.0f);
            o.w = fmaxf(ob * t.w + beta * acc[i].w, 0.0f);
            *(reinterpret_cast<float4*>(hout + (size_t)(node0 + n) * HIDDEN) + q) = o;
        }
    }
}

// ---------------------------------------------------------------------------
// Output (scalar-k): z = h @ W1 + b1 ; out = log_softmax(z)   (reads g_h)
// ---------------------------------------------------------------------------
__global__ __launch_bounds__(LTHREADS, 5)
void out_kernel(const float* __restrict__ W1,
                const float* __restrict__ b1,
                float* __restrict__ out) {
    __shared__ float sW[HIDDEN * HIDDEN];   // 9216 B
    __shared__ float sT[ONPB * HIDDEN];     // 30720 B (h, then Z in-place)
    __shared__ float sLS[ONPB];             // 640 B

    int tid = threadIdx.x;
    int node0 = blockIdx.x * ONPB;
    int base = node0 * HIDDEN;

    #pragma unroll
    for (int i = tid; i < HIDDEN * HIDDEN; i += LTHREADS)
        sW[i] = W1[i];
    {
        const float4* gh4 = reinterpret_cast<const float4*>(g_h + base);
        float4* sT4w = reinterpret_cast<float4*>(sT);
        for (int i = tid; i < ONPB * HIDDEN / 4; i += LTHREADS)
            sT4w[i] = gh4[i];
    }
    __syncthreads();

    int q = tid % 12;
    int m = tid / 12;
    const float4* sW4 = reinterpret_cast<const float4*>(sW);
    float4* sT4 = reinterpret_cast<float4*>(sT);
    float4 bv = reinterpret_cast<const float4*>(b1)[q];

    #pragma unroll
    for (int chunk = 0; chunk < 2; chunk++) {
        float4 acc[5];
        #pragma unroll
        for (int i = 0; i < 5; i++) acc[i] = bv;

        for (int k = 0; k < HIDDEN; k++) {
            float4 w = sW4[k * 12 + q];
            #pragma unroll
            for (int i = 0; i < 5; i++) {
                float a = sT[(m + 16 * (chunk * 5 + i)) * HIDDEN + k];
                acc[i].x = fmaf(a, w.x, acc[i].x);
                acc[i].y = fmaf(a, w.y, acc[i].y);
                acc[i].z = fmaf(a, w.z, acc[i].z);
                acc[i].w = fmaf(a, w.w, acc[i].w);
            }
        }
        __syncthreads();   // all reads of this chunk's source rows done
        #pragma unroll
        for (int i = 0; i < 5; i++) {
            int n = m + 16 * (chunk * 5 + i);
            sT4[n * 12 + q] = acc[i];
        }
    }
    __syncthreads();

    if (tid < ONPB) {
        float mx = -INFINITY;
        #pragma unroll
        for (int k = 0; k < HIDDEN; k++)
            mx = fmaxf(mx, sT[tid * HIDDEN + k]);
        float s = 0.0f;
        #pragma unroll
        for (int k = 0; k < HIDDEN; k++)
            s += expf(sT[tid * HIDDEN + k] - mx);
        sLS[tid] = mx + logf(s);
    }
    __syncthreads();

    #pragma unroll
    for (int i = 0; i < 10; i++) {
        int n = m + 16 * i;
        float ls = sLS[n];
        float4 z = sT4[n * 12 + q];
        float4 o;
        o.x = z.x - ls; o.y = z.y - ls; o.z = z.z - ls; o.w = z.w - ls;
        *(reinterpret_cast<float4*>(out + (size_t)base + n * HIDDEN) + q) = o;
    }
}

// ---------------------------------------------------------------------------
extern "C" void kernel_launch(void* const* d_in, const int* in_sizes, int n_in,
                              void* d_out, int out_size) {
    const float* x     = (const float*)d_in[0];
    const int*   ei    = (const int*)  d_in[1];
    const float* W0    = (const float*)d_in[2];
    const float* b0    = (const float*)d_in[3];
    const float* convW = (const float*)d_in[4];
    const float* W1    = (const float*)d_in[5];
    const float* b1    = (const float*)d_in[6];
    float* out = (float*)d_out;

    // beta_l = log(0.5/(l+1) + 1)
    const float betas[4] = {0.4054651081f, 0.2231435513f,
                            0.1541506798f, 0.1177830357f};

    const int it = 256;
    init_kernel<<<(N_EDGES + it - 1) / it, it>>>(x, W0, b0, ei);

    scanA_kernel<<<SCB, 256>>>();
    scanC_kernel<<<SCB, 1024>>>();

    const int ft = 256;
    fill_kernel<<<(N_EDGES / 4 + ft - 1) / ft, ft>>>(ei);

    const int node_blocks = N_NODES / NPB;   // 1250
    for (int l = 0; l < 4; l++)
        layer_kernel<<<node_blocks, FTHREADS>>>(convW + l * HIDDEN * HIDDEN,
                                                betas[l], l & 1);

    // layers 0..3: h path g_h -> g_hb -> g_h -> g_hb -> g_h (final in g_h)
    out_kernel<<<N_NODES / ONPB, LTHREADS>>>(W1, b1, out);
}

// round 15
// speedup vs baseline: 2.2780x; 1.0515x over previous
#include <cuda_runtime.h>
#include <math.h>

#define N_NODES 100000
#define N_EDGES 1600000
#define HIDDEN  48
#define ALPHA   0.1f
#define NPB     64          // nodes per block, layer kernel (100000 = 1562.5 -> 1563 blocks)
#define NLB     1563        // layer grid (last block covers 40 nodes: 100000 - 1562*64 = 32... see guard)
#define ONPB    160         // nodes per block, out kernel (100000 = 625 * 160)
#define LTHREADS 192        // out: 16 m-slots x 12 quads
#define FTHREADS 256        // layer: 64 gather groups of 4; gemm uses 192
#define ECAP    1408        // smem edge-index buffer (mean 1024)
#define SCB     100         // scan blocks
#define SCHUNK  1000        // elements per scan block

// Scratch (__device__ globals: allocation-free rule; zero-initialized at load)
// g_x0/g_h/g_hb are padded by one block so the tail block can run unguarded.
#define NPAD (NLB * NPB)    // 100032
__device__ float g_x0 [NPAD * HIDDEN];
__device__ float g_h  [NPAD * HIDDEN];
__device__ float g_hb [NPAD * HIDDEN];      // ping-pong buffer
__device__ int   g_cnt[N_NODES];            // ALWAYS zero at launch entry (scanC re-zeroes)
__device__ int   g_row[NPAD + 1];           // rows beyond N_NODES filled with total (empty rows)
__device__ int   g_cur[N_NODES];
__device__ int   g_esrc[N_EDGES];
__device__ int   g_part[SCB];

// ---------------------------------------------------------------------------
// Init (+fused histogram), vectorized: one thread per node-quad.
// Pads x0/h rows [N_NODES, NPAD) with zeros so the layer tail block is safe.
// ---------------------------------------------------------------------------
__global__ void init_kernel(const float* __restrict__ x,
                            const float* __restrict__ W0,
                            const float* __restrict__ b0,
                            const int* __restrict__ ei) {
    int idx = blockIdx.x * blockDim.x + threadIdx.x;
    if (idx < N_EDGES)
        atomicAdd(&g_cnt[ei[N_EDGES + idx]], 1);
    if (idx >= NPAD * 12) return;
    int n = idx / 12;
    int q = idx - n * 12;
    float4 v = make_float4(0.f, 0.f, 0.f, 0.f);
    if (n < N_NODES) {
        float x0v = x[n * 3 + 0], x1v = x[n * 3 + 1], x2v = x[n * 3 + 2];
        const float4* W04 = reinterpret_cast<const float4*>(W0);
        float4 w0 = W04[0 * 12 + q];
        float4 w1 = W04[1 * 12 + q];
        float4 w2 = W04[2 * 12 + q];
        float4 b  = reinterpret_cast<const float4*>(b0)[q];
        v.x = fmaxf(fmaf(x0v, w0.x, fmaf(x1v, w1.x, fmaf(x2v, w2.x, b.x))), 0.0f);
        v.y = fmaxf(fmaf(x0v, w0.y, fmaf(x1v, w1.y, fmaf(x2v, w2.y, b.y))), 0.0f);
        v.z = fmaxf(fmaf(x0v, w0.z, fmaf(x1v, w1.z, fmaf(x2v, w2.z, b.z))), 0.0f);
        v.w = fmaxf(fmaf(x0v, w0.w, fmaf(x1v, w1.w, fmaf(x2v, w2.w, b.w))), 0.0f);
    }
    reinterpret_cast<float4*>(g_x0)[idx] = v;
    reinterpret_cast<float4*>(g_h)[idx]  = v;
}

// ---------------------------------------------------------------------------
// Scan A: per-block sums of g_cnt
// ---------------------------------------------------------------------------
__global__ __launch_bounds__(256) void scanA_kernel() {
    __shared__ int s[256];
    int b = blockIdx.x, t = threadIdx.x;
    int sum = 0;
    for (int i = t; i < SCHUNK; i += 256) sum += g_cnt[b * SCHUNK + i];
    s[t] = sum;
    __syncthreads();
    for (int off = 128; off > 0; off >>= 1) {
        if (t < off) s[t] += s[t + off];
        __syncthreads();
    }
    if (t == 0) g_part[b] = s[0];
}

// ---------------------------------------------------------------------------
// Scan C: final exclusive scan; RE-ZEROES g_cnt; pads g_row tail with total.
// ---------------------------------------------------------------------------
__global__ __launch_bounds__(1024) void scanC_kernel() {
    __shared__ int s[1024];
    __shared__ int sOff;
    int b = blockIdx.x, t = threadIdx.x;
    if (t == 0) sOff = 0;
    __syncthreads();
    if (t < b) atomicAdd(&sOff, g_part[t]);   // b <= 99

    int i = b * SCHUNK + t;
    int c = (t < SCHUNK) ? g_cnt[i] : 0;
    s[t] = c;
    __syncthreads();
    for (int off = 1; off < 1024; off <<= 1) {
        int v = (t >= off) ? s[t - off] : 0;
        __syncthreads();
        s[t] += v;
        __syncthreads();
    }
    int off = sOff;
    if (t < SCHUNK) {
        int excl = s[t] - c + off;
        g_row[i] = excl;
        g_cur[i] = excl;
        g_cnt[i] = 0;                          // reset for next launch/replay
    }
    if (b == SCB - 1 && t == SCHUNK - 1) {
        int total = s[t] + off;                // == N_EDGES
        for (int k = N_NODES; k <= NPAD; k++)  // pad rows: empty (33 iters, once)
            g_row[k] = total;
    }
}

// ---------------------------------------------------------------------------
// CSR build: fill edge source lists (4 edges per thread, int4 loads)
// ---------------------------------------------------------------------------
__global__ void fill_kernel(const int* __restrict__ ei) {
    int t = blockIdx.x * blockDim.x + threadIdx.x;
    if (t >= N_EDGES / 4) return;
    int4 src = reinterpret_cast<const int4*>(ei)[t];
    int4 dst = reinterpret_cast<const int4*>(ei + N_EDGES)[t];
    int p0 = atomicAdd(&g_cur[dst.x], 1);
    int p1 = atomicAdd(&g_cur[dst.y], 1);
    int p2 = atomicAdd(&g_cur[dst.z], 1);
    int p3 = atomicAdd(&g_cur[dst.w], 1);
    g_esrc[p0] = src.x;
    g_esrc[p1] = src.y;
    g_esrc[p2] = src.z;
    g_esrc[p3] = src.w;
}

__device__ __forceinline__ void f4add(float4& a, const float4& b) {
    a.x += b.x; a.y += b.y; a.z += b.z; a.w += b.w;
}
__device__ __forceinline__ void f4add2(float4& a, const float4& b, const float4& c) {
    a.x += b.x + c.x; a.y += b.y + c.y; a.z += b.z + c.z; a.w += b.w + c.w;
}

// ---------------------------------------------------------------------------
// Fused layer: gather (4-lane interleaved groups, dynamic claiming, smem
// indices, 2-edge unroll) -> sT in smem -> scalar-k GEMM -> relu -> hout.
// NPB=64: smem ~27.5KB -> 8 blocks/SM; 1563 small blocks -> smooth drain.
// flip=0: read g_h, write g_hb.  flip=1: read g_hb, write g_h.
// ---------------------------------------------------------------------------
__global__ __launch_bounds__(FTHREADS)
void layer_kernel(const float* __restrict__ convW, float beta, int flip) {
    __shared__ float sW[HIDDEN * HIDDEN];   // 9216 B
    __shared__ float sT[NPB * HIDDEN];      // 12288 B
    __shared__ int   sE[ECAP];              // 5632 B
    __shared__ int   sR[NPB + 1];           // 260 B
    __shared__ int   sClaim;

    const float* __restrict__ hin  = flip ? g_hb : g_h;
    float*       __restrict__ hout = flip ? g_h  : g_hb;

    int tid = threadIdx.x;
    int node0 = blockIdx.x * NPB;

    #pragma unroll
    for (int i = tid; i < HIDDEN * HIDDEN; i += FTHREADS)
        sW[i] = convW[i];
    for (int i = tid; i <= NPB; i += FTHREADS)
        sR[i] = g_row[node0 + i];
    if (tid == 0) sClaim = 0;
    __syncthreads();

    int eStart = sR[0];
    int eCount = sR[NPB] - eStart;
    bool inSmem = (eCount <= ECAP);
    if (inSmem) {
        for (int i = tid; i < eCount; i += FTHREADS)
            sE[i] = g_esrc[eStart + i];
        __syncthreads();
    }

    int lane = tid & 31;
    int c = tid & 3;                          // interleave: float4 idx c, c+4, c+8
    unsigned submask = 0xFu << (lane & ~3);

    while (true) {
        int n = 0;
        if (c == 0) n = atomicAdd(&sClaim, 1);
        n = __shfl_sync(submask, n, 0, 4);
        if (n >= NPB) break;

        int rs = sR[n], re = sR[n + 1];
        float4 a0 = make_float4(0.f, 0.f, 0.f, 0.f);
        float4 a1 = a0, a2 = a0;

        if (inSmem) {
            int j = rs - eStart, je = re - eStart;
            for (; j + 2 <= je; j += 2) {
                int s0 = sE[j], s1 = sE[j + 1];
                const float4* p0 = reinterpret_cast<const float4*>(hin + (size_t)s0 * HIDDEN) + c;
                const float4* p1 = reinterpret_cast<const float4*>(hin + (size_t)s1 * HIDDEN) + c;
                float4 u0 = p0[0], u1 = p0[4], u2 = p0[8];
                float4 w0 = p1[0], w1 = p1[4], w2 = p1[8];
                f4add2(a0, u0, w0); f4add2(a1, u1, w1); f4add2(a2, u2, w2);
            }
            if (j < je) {
                int s0 = sE[j];
                const float4* p0 = reinterpret_cast<const float4*>(hin + (size_t)s0 * HIDDEN) + c;
                f4add(a0, p0[0]); f4add(a1, p0[4]); f4add(a2, p0[8]);
            }
        } else {
            int j = rs, je = re;
            for (; j + 2 <= je; j += 2) {
                int s0 = g_esrc[j], s1 = g_esrc[j + 1];
                const float4* p0 = reinterpret_cast<const float4*>(hin + (size_t)s0 * HIDDEN) + c;
                const float4* p1 = reinterpret_cast<const float4*>(hin + (size_t)s1 * HIDDEN) + c;
                float4 u0 = p0[0], u1 = p0[4], u2 = p0[8];
                float4 w0 = p1[0], w1 = p1[4], w2 = p1[8];
                f4add2(a0, u0, w0); f4add2(a1, u1, w1); f4add2(a2, u2, w2);
            }
            if (j < je) {
                int s0 = g_esrc[j];
                const float4* p0 = reinterpret_cast<const float4*>(hin + (size_t)s0 * HIDDEN) + c;
                f4add(a0, p0[0]); f4add(a1, p0[4]); f4add(a2, p0[8]);
            }
        }

        size_t nbase = (size_t)(node0 + n) * HIDDEN;
        const float4* px = reinterpret_cast<const float4*>(g_x0 + nbase) + c;
        float4 x0v0 = px[0], x0v1 = px[4], x0v2 = px[8];
        float4 t0, t1, t2;
        t0.x = (1.0f - ALPHA) * a0.x + ALPHA * x0v0.x;
        t0.y = (1.0f - ALPHA) * a0.y + ALPHA * x0v0.y;
        t0.z = (1.0f - ALPHA) * a0.z + ALPHA * x0v0.z;
        t0.w = (1.0f - ALPHA) * a0.w + ALPHA * x0v0.w;
        t1.x = (1.0f - ALPHA) * a1.x + ALPHA * x0v1.x;
        t1.y = (1.0f - ALPHA) * a1.y + ALPHA * x0v1.y;
        t1.z = (1.0f - ALPHA) * a1.z + ALPHA * x0v1.z;
        t1.w = (1.0f - ALPHA) * a1.w + ALPHA * x0v1.w;
        t2.x = (1.0f - ALPHA) * a2.x + ALPHA * x0v2.x;
        t2.y = (1.0f - ALPHA) * a2.y + ALPHA * x0v2.y;
        t2.z = (1.0f - ALPHA) * a2.z + ALPHA * x0v2.z;
        t2.w = (1.0f - ALPHA) * a2.w + ALPHA * x0v2.w;
        float4* pt = reinterpret_cast<float4*>(sT + n * HIDDEN) + c;
        pt[0] = t0; pt[4] = t1; pt[8] = t2;
    }
    __syncthreads();

    // --- scalar-k GEMM: 192 threads, thread (q, m) does quad q of 4 nodes ---
    if (tid < 192) {
        int q = tid % 12;          // output quad
        int m = tid / 12;          // 0..15; nodes m, m+16, m+32, m+48
        const float4* sW4 = reinterpret_cast<const float4*>(sW);
        float ob = 1.0f - beta;

        float4 acc[4];
        #pragma unroll
        for (int i = 0; i < 4; i++) acc[i] = make_float4(0.f, 0.f, 0.f, 0.f);

        for (int k = 0; k < HIDDEN; k++) {
            float4 w = sW4[k * 12 + q];
            #pragma unroll
            for (int i = 0; i < 4; i++) {
                float a = sT[(m + 16 * i) * HIDDEN + k];
                acc[i].x = fmaf(a, w.x, acc[i].x);
                acc[i].y = fmaf(a, w.y, acc[i].y);
                acc[i].z = fmaf(a, w.z, acc[i].z);
                acc[i].w = fmaf(a, w.w, acc[i].w);
            }
        }
        #pragma unroll
        for (int i = 0; i < 4; i++) {
            int n = m + 16 * i;
            float4 t = *(reinterpret_cast<const float4*>(sT + n * HIDDEN) + q);
            float4 o;
            o.x = fmaxf(ob * t.x + beta * acc[i].x, 0.0f);
            o.y = fmaxf(ob * t.y + beta * acc[i].y, 0.0f);
            o.z = fmaxf(ob * t.z + beta * acc[i].z, 0.0f);
            o.w = fmaxf(ob * t.w + beta * acc[i].w, 0.0f);
            *(reinterpret_cast<float4*>(hout + (size_t)(node0 + n) * HIDDEN) + q) = o;
        }
    }
}

// ---------------------------------------------------------------------------
// Output (scalar-k): z = h @ W1 + b1 ; out = log_softmax(z)   (reads g_h)
// ---------------------------------------------------------------------------
__global__ __launch_bounds__(LTHREADS, 5)
void out_kernel(const float* __restrict__ W1,
                const float* __restrict__ b1,
                float* __restrict__ out) {
    __shared__ float sW[HIDDEN * HIDDEN];   // 9216 B
    __shared__ float sT[ONPB * HIDDEN];     // 30720 B (h, then Z in-place)
    __shared__ float sLS[ONPB];             // 640 B

    int tid = threadIdx.x;
    int node0 = blockIdx.x * ONPB;
    int base = node0 * HIDDEN;

    #pragma unroll
    for (int i = tid; i < HIDDEN * HIDDEN; i += LTHREADS)
        sW[i] = W1[i];
    {
        const float4* gh4 = reinterpret_cast<const float4*>(g_h + base);
        float4* sT4w = reinterpret_cast<float4*>(sT);
        for (int i = tid; i < ONPB * HIDDEN / 4; i += LTHREADS)
            sT4w[i] = gh4[i];
    }
    __syncthreads();

    int q = tid % 12;
    int m = tid / 12;
    const float4* sW4 = reinterpret_cast<const float4*>(sW);
    float4* sT4 = reinterpret_cast<float4*>(sT);
    float4 bv = reinterpret_cast<const float4*>(b1)[q];

    #pragma unroll
    for (int chunk = 0; chunk < 2; chunk++) {
        float4 acc[5];
        #pragma unroll
        for (int i = 0; i < 5; i++) acc[i] = bv;

        for (int k = 0; k < HIDDEN; k++) {
            float4 w = sW4[k * 12 + q];
            #pragma unroll
            for (int i = 0; i < 5; i++) {
                float a = sT[(m + 16 * (chunk * 5 + i)) * HIDDEN + k];
                acc[i].x = fmaf(a, w.x, acc[i].x);
                acc[i].y = fmaf(a, w.y, acc[i].y);
                acc[i].z = fmaf(a, w.z, acc[i].z);
                acc[i].w = fmaf(a, w.w, acc[i].w);
            }
        }
        __syncthreads();   // all reads of this chunk's source rows done
        #pragma unroll
        for (int i = 0; i < 5; i++) {
            int n = m + 16 * (chunk * 5 + i);
            sT4[n * 12 + q] = acc[i];
        }
    }
    __syncthreads();

    if (tid < ONPB) {
        float mx = -INFINITY;
        #pragma unroll
        for (int k = 0; k < HIDDEN; k++)
            mx = fmaxf(mx, sT[tid * HIDDEN + k]);
        float s = 0.0f;
        #pragma unroll
        for (int k = 0; k < HIDDEN; k++)
            s += expf(sT[tid * HIDDEN + k] - mx);
        sLS[tid] = mx + logf(s);
    }
    __syncthreads();

    #pragma unroll
    for (int i = 0; i < 10; i++) {
        int n = m + 16 * i;
        float ls = sLS[n];
        float4 z = sT4[n * 12 + q];
        float4 o;
        o.x = z.x - ls; o.y = z.y - ls; o.z = z.z - ls; o.w = z.w - ls;
        *(reinterpret_cast<float4*>(out + (size_t)base + n * HIDDEN) + q) = o;
    }
}

// ---------------------------------------------------------------------------
extern "C" void kernel_launch(void* const* d_in, const int* in_sizes, int n_in,
                              void* d_out, int out_size) {
    const float* x     = (const float*)d_in[0];
    const int*   ei    = (const int*)  d_in[1];
    const float* W0    = (const float*)d_in[2];
    const float* b0    = (const float*)d_in[3];
    const float* convW = (const float*)d_in[4];
    const float* W1    = (const float*)d_in[5];
    const float* b1    = (const float*)d_in[6];
    float* out = (float*)d_out;

    // beta_l = log(0.5/(l+1) + 1)
    const float betas[4] = {0.4054651081f, 0.2231435513f,
                            0.1541506798f, 0.1177830357f};

    const int it = 256;
    const int ig = (NPAD * 12 > N_EDGES ? NPAD * 12 : N_EDGES);
    init_kernel<<<(ig + it - 1) / it, it>>>(x, W0, b0, ei);

    scanA_kernel<<<SCB, 256>>>();
    scanC_kernel<<<SCB, 1024>>>();

    const int ft = 256;
    fill_kernel<<<(N_EDGES / 4 + ft - 1) / ft, ft>>>(ei);

    for (int l = 0; l < 4; l++)
        layer_kernel<<<NLB, FTHREADS>>>(convW + l * HIDDEN * HIDDEN,
                                        betas[l], l & 1);

    // layers 0..3: h path g_h -> g_hb -> g_h -> g_hb -> g_h (final in g_h)
    out_kernel<<<N_NODES / ONPB, LTHREADS>>>(W1, b1, out);
}

// round 16
// speedup vs baseline: 2.4413x; 1.0717x over previous
#include <cuda_runtime.h>
#include <math.h>

#define N_NODES 100000
#define N_EDGES 1600000
#define HIDDEN  48
#define ALPHA   0.1f
#define NPB     64          // nodes per block, layer kernel
#define NLB     1563        // layer grid (ceil(100000/64))
#define LTHREADS 192
#define FTHREADS 256        // layer: 64 gather groups of 4; gemm uses 192
#define ECAP    1408        // smem edge-index buffer (mean 1024)
#define SCB     100         // scan blocks
#define SCHUNK  1000        // elements per scan block

// Scratch (__device__ globals: allocation-free rule; zero-initialized at load)
// g_x0/g_h/g_hb padded by one block so the tail block can run unguarded.
#define NPAD (NLB * NPB)    // 100032
__device__ float g_x0 [NPAD * HIDDEN];
__device__ float g_h  [NPAD * HIDDEN];
__device__ float g_hb [NPAD * HIDDEN];      // ping-pong buffer
__device__ int   g_cnt[N_NODES];            // ALWAYS zero at launch entry (scanC re-zeroes)
__device__ int   g_row[NPAD + 1];           // rows beyond N_NODES filled with total (empty)
__device__ int   g_cur[N_NODES];
__device__ int   g_esrc[N_EDGES];
__device__ int   g_part[SCB];

// ---------------------------------------------------------------------------
// Init (+fused histogram), vectorized: one thread per node-quad.
// Pads x0/h rows [N_NODES, NPAD) with zeros.
// ---------------------------------------------------------------------------
__global__ void init_kernel(const float* __restrict__ x,
                            const float* __restrict__ W0,
                            const float* __restrict__ b0,
                            const int* __restrict__ ei) {
    int idx = blockIdx.x * blockDim.x + threadIdx.x;
    if (idx < N_EDGES)
        atomicAdd(&g_cnt[ei[N_EDGES + idx]], 1);
    if (idx >= NPAD * 12) return;
    int n = idx / 12;
    int q = idx - n * 12;
    float4 v = make_float4(0.f, 0.f, 0.f, 0.f);
    if (n < N_NODES) {
        float x0v = x[n * 3 + 0], x1v = x[n * 3 + 1], x2v = x[n * 3 + 2];
        const float4* W04 = reinterpret_cast<const float4*>(W0);
        float4 w0 = W04[0 * 12 + q];
        float4 w1 = W04[1 * 12 + q];
        float4 w2 = W04[2 * 12 + q];
        float4 b  = reinterpret_cast<const float4*>(b0)[q];
        v.x = fmaxf(fmaf(x0v, w0.x, fmaf(x1v, w1.x, fmaf(x2v, w2.x, b.x))), 0.0f);
        v.y = fmaxf(fmaf(x0v, w0.y, fmaf(x1v, w1.y, fmaf(x2v, w2.y, b.y))), 0.0f);
        v.z = fmaxf(fmaf(x0v, w0.z, fmaf(x1v, w1.z, fmaf(x2v, w2.z, b.z))), 0.0f);
        v.w = fmaxf(fmaf(x0v, w0.w, fmaf(x1v, w1.w, fmaf(x2v, w2.w, b.w))), 0.0f);
    }
    reinterpret_cast<float4*>(g_x0)[idx] = v;
    reinterpret_cast<float4*>(g_h)[idx]  = v;
}

// ---------------------------------------------------------------------------
// Scan A: per-block sums of g_cnt
// ---------------------------------------------------------------------------
__global__ __launch_bounds__(256) void scanA_kernel() {
    __shared__ int s[256];
    int b = blockIdx.x, t = threadIdx.x;
    int sum = 0;
    for (int i = t; i < SCHUNK; i += 256) sum += g_cnt[b * SCHUNK + i];
    s[t] = sum;
    __syncthreads();
    for (int off = 128; off > 0; off >>= 1) {
        if (t < off) s[t] += s[t + off];
        __syncthreads();
    }
    if (t == 0) g_part[b] = s[0];
}

// ---------------------------------------------------------------------------
// Scan C: final exclusive scan; RE-ZEROES g_cnt; pads g_row tail with total.
// ---------------------------------------------------------------------------
__global__ __launch_bounds__(1024) void scanC_kernel() {
    __shared__ int s[1024];
    __shared__ int sOff;
    int b = blockIdx.x, t = threadIdx.x;
    if (t == 0) sOff = 0;
    __syncthreads();
    if (t < b) atomicAdd(&sOff, g_part[t]);   // b <= 99

    int i = b * SCHUNK + t;
    int c = (t < SCHUNK) ? g_cnt[i] : 0;
    s[t] = c;
    __syncthreads();
    for (int off = 1; off < 1024; off <<= 1) {
        int v = (t >= off) ? s[t - off] : 0;
        __syncthreads();
        s[t] += v;
        __syncthreads();
    }
    int off = sOff;
    if (t < SCHUNK) {
        int excl = s[t] - c + off;
        g_row[i] = excl;
        g_cur[i] = excl;
        g_cnt[i] = 0;                          // reset for next launch/replay
    }
    if (b == SCB - 1 && t == SCHUNK - 1) {
        int total = s[t] + off;                // == N_EDGES
        for (int k = N_NODES; k <= NPAD; k++)  // pad rows: empty
            g_row[k] = total;
    }
}

// ---------------------------------------------------------------------------
// CSR build: fill edge source lists (4 edges per thread, int4 loads)
// ---------------------------------------------------------------------------
__global__ void fill_kernel(const int* __restrict__ ei) {
    int t = blockIdx.x * blockDim.x + threadIdx.x;
    if (t >= N_EDGES / 4) return;
    int4 src = reinterpret_cast<const int4*>(ei)[t];
    int4 dst = reinterpret_cast<const int4*>(ei + N_EDGES)[t];
    int p0 = atomicAdd(&g_cur[dst.x], 1);
    int p1 = atomicAdd(&g_cur[dst.y], 1);
    int p2 = atomicAdd(&g_cur[dst.z], 1);
    int p3 = atomicAdd(&g_cur[dst.w], 1);
    g_esrc[p0] = src.x;
    g_esrc[p1] = src.y;
    g_esrc[p2] = src.z;
    g_esrc[p3] = src.w;
}

__device__ __forceinline__ void f4add(float4& a, const float4& b) {
    a.x += b.x; a.y += b.y; a.z += b.z; a.w += b.w;
}
__device__ __forceinline__ void f4add2(float4& a, const float4& b, const float4& c) {
    a.x += b.x + c.x; a.y += b.y + c.y; a.z += b.z + c.z; a.w += b.w + c.w;
}

// ---------------------------------------------------------------------------
// Shared gather device function: fills sT with t = 0.9*agg + 0.1*x0.
// Caller provides smem buffers; hin is the layer input feature matrix.
// ---------------------------------------------------------------------------
__device__ __forceinline__ void gather_into_sT(
    const float* __restrict__ hin, int node0,
    float* sT, int* sE, int* sR, int* sClaim, int tid)
{
    for (int i = tid; i <= NPB; i += FTHREADS)
        sR[i] = g_row[node0 + i];
    if (tid == 0) *sClaim = 0;
    __syncthreads();

    int eStart = sR[0];
    int eCount = sR[NPB] - eStart;
    bool inSmem = (eCount <= ECAP);
    if (inSmem) {
        for (int i = tid; i < eCount; i += FTHREADS)
            sE[i] = g_esrc[eStart + i];
        __syncthreads();
    }

    int lane = tid & 31;
    int c = tid & 3;                          // interleave: float4 idx c, c+4, c+8
    unsigned submask = 0xFu << (lane & ~3);

    while (true) {
        int n = 0;
        if (c == 0) n = atomicAdd(sClaim, 1);
        n = __shfl_sync(submask, n, 0, 4);
        if (n >= NPB) break;

        int rs = sR[n], re = sR[n + 1];
        float4 a0 = make_float4(0.f, 0.f, 0.f, 0.f);
        float4 a1 = a0, a2 = a0;

        if (inSmem) {
            int j = rs - eStart, je = re - eStart;
            for (; j + 2 <= je; j += 2) {
                int s0 = sE[j], s1 = sE[j + 1];
                const float4* p0 = reinterpret_cast<const float4*>(hin + (size_t)s0 * HIDDEN) + c;
                const float4* p1 = reinterpret_cast<const float4*>(hin + (size_t)s1 * HIDDEN) + c;
                float4 u0 = p0[0], u1 = p0[4], u2 = p0[8];
                float4 w0 = p1[0], w1 = p1[4], w2 = p1[8];
                f4add2(a0, u0, w0); f4add2(a1, u1, w1); f4add2(a2, u2, w2);
            }
            if (j < je) {
                int s0 = sE[j];
                const float4* p0 = reinterpret_cast<const float4*>(hin + (size_t)s0 * HIDDEN) + c;
                f4add(a0, p0[0]); f4add(a1, p0[4]); f4add(a2, p0[8]);
            }
        } else {
            int j = rs, je = re;
            for (; j + 2 <= je; j += 2) {
                int s0 = g_esrc[j], s1 = g_esrc[j + 1];
                const float4* p0 = reinterpret_cast<const float4*>(hin + (size_t)s0 * HIDDEN) + c;
                const float4* p1 = reinterpret_cast<const float4*>(hin + (size_t)s1 * HIDDEN) + c;
                float4 u0 = p0[0], u1 = p0[4], u2 = p0[8];
                float4 w0 = p1[0], w1 = p1[4], w2 = p1[8];
                f4add2(a0, u0, w0); f4add2(a1, u1, w1); f4add2(a2, u2, w2);
            }
            if (j < je) {
                int s0 = g_esrc[j];
                const float4* p0 = reinterpret_cast<const float4*>(hin + (size_t)s0 * HIDDEN) + c;
                f4add(a0, p0[0]); f4add(a1, p0[4]); f4add(a2, p0[8]);
            }
        }

        size_t nbase = (size_t)(node0 + n) * HIDDEN;
        const float4* px = reinterpret_cast<const float4*>(g_x0 + nbase) + c;
        float4 x0v0 = px[0], x0v1 = px[4], x0v2 = px[8];
        float4 t0, t1, t2;
        t0.x = (1.0f - ALPHA) * a0.x + ALPHA * x0v0.x;
        t0.y = (1.0f - ALPHA) * a0.y + ALPHA * x0v0.y;
        t0.z = (1.0f - ALPHA) * a0.z + ALPHA * x0v0.z;
        t0.w = (1.0f - ALPHA) * a0.w + ALPHA * x0v0.w;
        t1.x = (1.0f - ALPHA) * a1.x + ALPHA * x0v1.x;
        t1.y = (1.0f - ALPHA) * a1.y + ALPHA * x0v1.y;
        t1.z = (1.0f - ALPHA) * a1.z + ALPHA * x0v1.z;
        t1.w = (1.0f - ALPHA) * a1.w + ALPHA * x0v1.w;
        t2.x = (1.0f - ALPHA) * a2.x + ALPHA * x0v2.x;
        t2.y = (1.0f - ALPHA) * a2.y + ALPHA * x0v2.y;
        t2.z = (1.0f - ALPHA) * a2.z + ALPHA * x0v2.z;
        t2.w = (1.0f - ALPHA) * a2.w + ALPHA * x0v2.w;
        float4* pt = reinterpret_cast<float4*>(sT + n * HIDDEN) + c;
        pt[0] = t0; pt[4] = t1; pt[8] = t2;
    }
    __syncthreads();
}

// ---------------------------------------------------------------------------
// Layers 0..2: gather -> sT -> scalar-k GEMM -> relu -> hout.
// flip=0: read g_h, write g_hb.  flip=1: read g_hb, write g_h.
// ---------------------------------------------------------------------------
__global__ __launch_bounds__(FTHREADS)
void layer_kernel(const float* __restrict__ convW, float beta, int flip) {
    __shared__ float sW[HIDDEN * HIDDEN];   // 9216 B
    __shared__ float sT[NPB * HIDDEN];      // 12288 B
    __shared__ int   sE[ECAP];              // 5632 B
    __shared__ int   sR[NPB + 1];
    __shared__ int   sClaim;

    const float* __restrict__ hin  = flip ? g_hb : g_h;
    float*       __restrict__ hout = flip ? g_h  : g_hb;

    int tid = threadIdx.x;
    int node0 = blockIdx.x * NPB;

    #pragma unroll
    for (int i = tid; i < HIDDEN * HIDDEN; i += FTHREADS)
        sW[i] = convW[i];

    gather_into_sT(hin, node0, sT, sE, sR, &sClaim, tid);

    // --- scalar-k GEMM: 192 threads, thread (q, m) does quad q of 4 nodes ---
    if (tid < 192) {
        int q = tid % 12;
        int m = tid / 12;          // 0..15; nodes m, m+16, m+32, m+48
        const float4* sW4 = reinterpret_cast<const float4*>(sW);
        float ob = 1.0f - beta;

        float4 acc[4];
        #pragma unroll
        for (int i = 0; i < 4; i++) acc[i] = make_float4(0.f, 0.f, 0.f, 0.f);

        for (int k = 0; k < HIDDEN; k++) {
            float4 w = sW4[k * 12 + q];
            #pragma unroll
            for (int i = 0; i < 4; i++) {
                float a = sT[(m + 16 * i) * HIDDEN + k];
                acc[i].x = fmaf(a, w.x, acc[i].x);
                acc[i].y = fmaf(a, w.y, acc[i].y);
                acc[i].z = fmaf(a, w.z, acc[i].z);
                acc[i].w = fmaf(a, w.w, acc[i].w);
            }
        }
        #pragma unroll
        for (int i = 0; i < 4; i++) {
            int n = m + 16 * i;
            float4 t = *(reinterpret_cast<const float4*>(sT + n * HIDDEN) + q);
            float4 o;
            o.x = fmaxf(ob * t.x + beta * acc[i].x, 0.0f);
            o.y = fmaxf(ob * t.y + beta * acc[i].y, 0.0f);
            o.z = fmaxf(ob * t.z + beta * acc[i].z, 0.0f);
            o.w = fmaxf(ob * t.w + beta * acc[i].w, 0.0f);
            *(reinterpret_cast<float4*>(hout + (size_t)(node0 + n) * HIDDEN) + q) = o;
        }
    }
}

// ---------------------------------------------------------------------------
// FINAL layer (l=3) fused with output head:
// gather(g_hb) -> GEMM(convW3) -> h (in sT, register-staged) ->
// GEMM(W1)+b1 -> z (in sT) -> log_softmax -> out. No g_h write, no out read.
// ---------------------------------------------------------------------------
__global__ __launch_bounds__(FTHREADS)
void layer_final_kernel(const float* __restrict__ convW, float beta,
                        const float* __restrict__ W1,
                        const float* __restrict__ b1,
                        float* __restrict__ out) {
    __shared__ float sW [HIDDEN * HIDDEN];  // 9216 B (convW3)
    __shared__ float sW1[HIDDEN * HIDDEN];  // 9216 B (W1)
    __shared__ float sT [NPB * HIDDEN];     // 12288 B (t -> h -> z in place)
    __shared__ int   sE[ECAP];              // 5632 B
    __shared__ int   sR[NPB + 1];
    __shared__ float sLS[NPB];
    __shared__ int   sClaim;

    int tid = threadIdx.x;
    int node0 = blockIdx.x * NPB;

    #pragma unroll
    for (int i = tid; i < HIDDEN * HIDDEN; i += FTHREADS) {
        sW[i]  = convW[i];
        sW1[i] = W1[i];
    }

    gather_into_sT(g_hb, node0, sT, sE, sR, &sClaim, tid);

    int q = tid % 12;
    int m = tid / 12;              // 0..15 for tid<192
    const float4* sW4  = reinterpret_cast<const float4*>(sW);
    const float4* sW14 = reinterpret_cast<const float4*>(sW1);
    float4* sT4 = reinterpret_cast<float4*>(sT);

    // --- GEMM1: h = relu((1-beta)*t + beta * t@convW3), staged in registers ---
    float4 hacc[4];
    if (tid < 192) {
        float ob = 1.0f - beta;
        float4 acc[4];
        #pragma unroll
        for (int i = 0; i < 4; i++) acc[i] = make_float4(0.f, 0.f, 0.f, 0.f);
        for (int k = 0; k < HIDDEN; k++) {
            float4 w = sW4[k * 12 + q];
            #pragma unroll
            for (int i = 0; i < 4; i++) {
                float a = sT[(m + 16 * i) * HIDDEN + k];
                acc[i].x = fmaf(a, w.x, acc[i].x);
                acc[i].y = fmaf(a, w.y, acc[i].y);
                acc[i].z = fmaf(a, w.z, acc[i].z);
                acc[i].w = fmaf(a, w.w, acc[i].w);
            }
        }
        #pragma unroll
        for (int i = 0; i < 4; i++) {
            int n = m + 16 * i;
            float4 t = sT4[n * 12 + q];
            hacc[i].x = fmaxf(ob * t.x + beta * acc[i].x, 0.0f);
            hacc[i].y = fmaxf(ob * t.y + beta * acc[i].y, 0.0f);
            hacc[i].z = fmaxf(ob * t.z + beta * acc[i].z, 0.0f);
            hacc[i].w = fmaxf(ob * t.w + beta * acc[i].w, 0.0f);
        }
    }
    __syncthreads();               // all GEMM1 reads of sT complete
    if (tid < 192) {
        #pragma unroll
        for (int i = 0; i < 4; i++)
            sT4[(m + 16 * i) * 12 + q] = hacc[i];
    }
    __syncthreads();               // sT now holds h

    // --- GEMM2: z = h @ W1 + b1, staged in registers ---
    float4 zacc[4];
    if (tid < 192) {
        float4 bv = reinterpret_cast<const float4*>(b1)[q];
        #pragma unroll
        for (int i = 0; i < 4; i++) zacc[i] = bv;
        for (int k = 0; k < HIDDEN; k++) {
            float4 w = sW14[k * 12 + q];
            #pragma unroll
            for (int i = 0; i < 4; i++) {
                float a = sT[(m + 16 * i) * HIDDEN + k];
                zacc[i].x = fmaf(a, w.x, zacc[i].x);
                zacc[i].y = fmaf(a, w.y, zacc[i].y);
                zacc[i].z = fmaf(a, w.z, zacc[i].z);
                zacc[i].w = fmaf(a, w.w, zacc[i].w);
            }
        }
    }
    __syncthreads();               // all GEMM2 reads of sT complete
    if (tid < 192) {
        #pragma unroll
        for (int i = 0; i < 4; i++)
            sT4[(m + 16 * i) * 12 + q] = zacc[i];
    }
    __syncthreads();               // sT now holds z

    // --- log-softmax per node ---
    if (tid < NPB) {
        float mx = -INFINITY;
        #pragma unroll
        for (int k = 0; k < HIDDEN; k++)
            mx = fmaxf(mx, sT[tid * HIDDEN + k]);
        float s = 0.0f;
        #pragma unroll
        for (int k = 0; k < HIDDEN; k++)
            s += expf(sT[tid * HIDDEN + k] - mx);
        sLS[tid] = mx + logf(s);
    }
    __syncthreads();

    if (tid < 192) {
        #pragma unroll
        for (int i = 0; i < 4; i++) {
            int n = m + 16 * i;
            int node = node0 + n;
            if (node < N_NODES) {
                float ls = sLS[n];
                float4 z = sT4[n * 12 + q];
                float4 o;
                o.x = z.x - ls; o.y = z.y - ls; o.z = z.z - ls; o.w = z.w - ls;
                *(reinterpret_cast<float4*>(out + (size_t)node * HIDDEN) + q) = o;
            }
        }
    }
}

// ---------------------------------------------------------------------------
extern "C" void kernel_launch(void* const* d_in, const int* in_sizes, int n_in,
                              void* d_out, int out_size) {
    const float* x     = (const float*)d_in[0];
    const int*   ei    = (const int*)  d_in[1];
    const float* W0    = (const float*)d_in[2];
    const float* b0    = (const float*)d_in[3];
    const float* convW = (const float*)d_in[4];
    const float* W1    = (const float*)d_in[5];
    const float* b1    = (const float*)d_in[6];
    float* out = (float*)d_out;

    // beta_l = log(0.5/(l+1) + 1)
    const float betas[4] = {0.4054651081f, 0.2231435513f,
                            0.1541506798f, 0.1177830357f};

    const int it = 256;
    const int ig = (NPAD * 12 > N_EDGES ? NPAD * 12 : N_EDGES);
    init_kernel<<<(ig + it - 1) / it, it>>>(x, W0, b0, ei);

    scanA_kernel<<<SCB, 256>>>();
    scanC_kernel<<<SCB, 1024>>>();

    const int ft = 256;
    fill_kernel<<<(N_EDGES / 4 + ft - 1) / ft, ft>>>(ei);

    // layers 0..2: h path g_h -> g_hb -> g_h -> g_hb
    for (int l = 0; l < 3; l++)
        layer_kernel<<<NLB, FTHREADS>>>(convW + l * HIDDEN * HIDDEN,
                                        betas[l], l & 1);

    // layer 3 fused with output head: reads g_hb, writes out directly
    layer_final_kernel<<<NLB, FTHREADS>>>(convW + 3 * HIDDEN * HIDDEN,
                                          betas[3], W1, b1, out);
}